// round 8
// baseline (speedup 1.0000x reference)
#include <cuda_runtime.h>
#include <cstdint>
#include <math.h>

#define DIM 256
#define TM 64
#define THREADS 256
#define KC 32
#define NJOBS 32                 // 4 passes x 8 chunks

#define PX 36                    // smem row stride (floats): 36%32==4 -> LDSM conflict-free
#define PW 36
#define GW 256                   // g_Wt gmem row stride
#define XS_FLOATS (TM * PX)      // 2304
#define WS_FLOATS (256 * PW)     // 9216
#define BUF_FLOATS (XS_FLOATS + WS_FLOATS)      // 11520 -> 46080 B
#define BUF_BYTES (BUF_FLOATS * 4)
#define SMEM_BYTES (2 * BUF_BYTES)              // 92160 B -> 2 CTAs/SM

__device__ float g_Wt[4][256 * GW];   // [n][k], transposed + tf32-rna-rounded

__device__ __forceinline__ uint32_t smem_u32(const void* p) {
    uint32_t a;
    asm("{ .reg .u64 t; cvta.to.shared.u64 t, %1; cvt.u32.u64 %0, t; }" : "=r"(a) : "l"(p));
    return a;
}
__device__ __forceinline__ void cp16(uint32_t s, const float* g) {
    asm volatile("cp.async.cg.shared.global [%0], [%1], 16;" :: "r"(s), "l"(g));
}
#define CP_COMMIT() asm volatile("cp.async.commit_group;" ::: "memory")
#define CP_WAIT(n)  asm volatile("cp.async.wait_group %0;" :: "n"(n) : "memory")

__device__ __forceinline__ uint32_t to_tf32(float x) {
    uint32_t r;
    asm("cvt.rna.tf32.f32 %0, %1;" : "=r"(r) : "f"(x));
    return r;
}
__device__ __forceinline__ void ldsm4(uint32_t* r, uint32_t addr) {
    asm volatile("ldmatrix.sync.aligned.m8n8.x4.shared.b16 {%0,%1,%2,%3}, [%4];"
                 : "=r"(r[0]), "=r"(r[1]), "=r"(r[2]), "=r"(r[3]) : "r"(addr));
}
__device__ __forceinline__ void mma8(float* c, const uint32_t* a, const uint32_t* b) {
    asm volatile(
        "mma.sync.aligned.m16n8k8.row.col.f32.tf32.tf32.f32 "
        "{%0,%1,%2,%3}, {%4,%5,%6,%7}, {%8,%9}, {%0,%1,%2,%3};"
        : "+f"(c[0]), "+f"(c[1]), "+f"(c[2]), "+f"(c[3])
        : "r"(a[0]), "r"(a[1]), "r"(a[2]), "r"(a[3]), "r"(b[0]), "r"(b[1]));
}

// ---- one KC=32 chunk: acc(32x64 warptile) += X @ W ----
// krot: per-warp k-step rotation; nrot: per-warp B-tile rotation (de-phasing).
template <bool SCALE>
__device__ __forceinline__ void gemm_chunk(uint32_t a_base, uint32_t b_base,
                                           float (&acc)[2][8][4],
                                           const float (&sc)[2][2],
                                           int krot, int nrot) {
#pragma unroll
    for (int kk = 0; kk < 4; ++kk) {
        const int ks = (kk + krot) & 3;
        uint32_t ua[2][4];
        ldsm4(ua[0], a_base + ks * 32);
        ldsm4(ua[1], a_base + 16 * PX * 4 + ks * 32);
        if (SCALE) {
#pragma unroll
            for (int mt = 0; mt < 2; ++mt) {
                ua[mt][0] = __float_as_uint(__uint_as_float(ua[mt][0]) * sc[mt][0]);
                ua[mt][1] = __float_as_uint(__uint_as_float(ua[mt][1]) * sc[mt][1]);
                ua[mt][2] = __float_as_uint(__uint_as_float(ua[mt][2]) * sc[mt][0]);
                ua[mt][3] = __float_as_uint(__uint_as_float(ua[mt][3]) * sc[mt][1]);
            }
        }
#pragma unroll
        for (int nn = 0; nn < 4; ++nn) {
            const int nt2 = (nn + nrot) & 3;
            uint32_t b[4];                         // nt = 2*nt2, 2*nt2+1
            ldsm4(b, b_base + nt2 * (16 * PW * 4) + ks * 32);
            mma8(acc[0][2 * nt2],     ua[0], b);
            mma8(acc[1][2 * nt2],     ua[1], b);
            mma8(acc[0][2 * nt2 + 1], ua[0], b + 2);
            mma8(acc[1][2 * nt2 + 1], ua[1], b + 2);
        }
    }
}

__device__ __forceinline__ void zero_acc(float (&acc)[2][8][4]) {
#pragma unroll
    for (int mt = 0; mt < 2; ++mt)
#pragma unroll
        for (int nt = 0; nt < 8; ++nt)
#pragma unroll
            for (int q = 0; q < 4; ++q) acc[mt][nt][q] = 0.f;
}

__device__ __forceinline__ void gate_dot(const float* __restrict__ Xo,
                                         const float (&acc)[2][8][4], int g,
                                         int wm, int wn, int lq, int lr,
                                         float (*s_g)[4][TM]) {
    float pr[2][2] = {{0.f, 0.f}, {0.f, 0.f}};
#pragma unroll
    for (int mt = 0; mt < 2; ++mt) {
        const int r0 = wm * 32 + mt * 16 + lq;
#pragma unroll
        for (int nt = 0; nt < 8; ++nt) {
            const int cb = wn * 64 + nt * 8 + lr * 2;
            float2 v0 = *reinterpret_cast<const float2*>(Xo + (size_t)r0 * DIM + cb);
            float2 v1 = *reinterpret_cast<const float2*>(Xo + (size_t)(r0 + 8) * DIM + cb);
            pr[mt][0] += acc[mt][nt][0] * v0.x + acc[mt][nt][1] * v0.y;
            pr[mt][1] += acc[mt][nt][2] * v1.x + acc[mt][nt][3] * v1.y;
        }
    }
#pragma unroll
    for (int off = 1; off <= 2; off <<= 1)
#pragma unroll
        for (int mt = 0; mt < 2; ++mt) {
            pr[mt][0] += __shfl_xor_sync(0xFFFFFFFFu, pr[mt][0], off);
            pr[mt][1] += __shfl_xor_sync(0xFFFFFFFFu, pr[mt][1], off);
        }
    if (lr == 0) {
#pragma unroll
        for (int mt = 0; mt < 2; ++mt) {
            s_g[g][wn][wm * 32 + mt * 16 + lq] = pr[mt][0];
            s_g[g][wn][wm * 32 + mt * 16 + lq + 8] = pr[mt][1];
        }
    }
}

__global__ void __launch_bounds__(THREADS, 2)
fused_mma_kernel(const float* __restrict__ i0, const float* __restrict__ i1,
                 float* __restrict__ out) {
    extern __shared__ float dyn[];
    __shared__ float s_g[2][4][TM];
    __shared__ float s_sc[2][TM];

    const int tid = threadIdx.x;
    const int l = tid & 31, w = tid >> 5;
    const int wm = w >> 2, wn = w & 3;         // m-split 2, n-split 4
    const int lq = l >> 2, lr = l & 3;
    const int krot = w & 3;                    // de-phase k-steps across warps
    const int nrot = wm * 2 + (w & 1);         // de-phase B tiles among wn-sharers
    const size_t rowbase = (size_t)blockIdx.x * TM;
    const float* X0g = i0 + rowbase * DIM;
    const float* X1g = i1 + rowbase * DIM;
    const uint32_t sb = smem_u32(dyn);

    // per-lane LDSM addressing
    const int arow = ((l >> 3) & 1) * 8 + (l & 7);
    const int acg  = (l >> 4) & 1;
    const int brow = ((l >> 4) & 1) * 8 + (l & 7);
    const int bcg  = (l >> 3) & 1;
    const uint32_t a_off = (uint32_t)((wm * 32 + arow) * PX + acg * 4) * 4;
    const uint32_t b_off = (uint32_t)(XS_FLOATS + (wn * 64 + brow) * PW + bcg * 4) * 4;

    // jobs 0..31: pass p=j>>3, chunk c=j&7
    //  p0: A=X1,B=attn1 -> g0 dot X0    p1: A=X0,B=attn2 -> g1 dot X1
    //  p2: A=X0,B=W1 (scale s0)         p3: A=X1,B=W2 (scale s1)
    auto stage = [&](int j) {
        const int p = j >> 3, c = j & 7;
        const float* As = (p == 0 || p == 3) ? X1g : X0g;
        const float* Bs = g_Wt[p];
        const uint32_t base = sb + (uint32_t)(j & 1) * BUF_BYTES;
#pragma unroll
        for (int t = 0; t < 2; ++t) {          // X chunk: 64 x 32
            const int id = tid + t * THREADS;
            const int r = id >> 3, c4 = (id & 7) << 2;
            cp16(base + (uint32_t)(r * PX + c4) * 4, As + (size_t)r * DIM + c * 32 + c4);
        }
#pragma unroll
        for (int t = 0; t < 8; ++t) {          // Wt chunk: 256 n x 32 k
            const int id = tid + t * THREADS;
            const int n = id >> 3, k4 = (id & 7) << 2;
            cp16(base + (uint32_t)(XS_FLOATS + n * PW + k4) * 4,
                 Bs + (size_t)n * GW + c * 32 + k4);
        }
        CP_COMMIT();
    };

    float acc[2][8][4];
    zero_acc(acc);
    float sc[2][2] = {{1.f, 1.f}, {1.f, 1.f}};

    stage(0);
    stage(1);

    for (int j = 0; j < NJOBS; ++j) {
        if (j == NJOBS - 1) { CP_WAIT(0); } else { CP_WAIT(1); }
        __syncthreads();
        const uint32_t base = sb + (uint32_t)(j & 1) * BUF_BYTES;
        if (j >= 16) gemm_chunk<true>(base + a_off, base + b_off, acc, sc, krot, nrot);
        else         gemm_chunk<false>(base + a_off, base + b_off, acc, sc, krot, nrot);

        if (j == 7) {                          // g0 = rowdot(U0, X0)
            gate_dot(X0g, acc, 0, wm, wn, lq, lr, s_g);
            zero_acc(acc);
        }
        if (j == 15) {                         // g1; sigmoid; load s0 scales
            gate_dot(X1g, acc, 1, wm, wn, lq, lr, s_g);
            __syncthreads();
            if (tid < TM) {
                const float g0 = s_g[0][0][tid] + s_g[0][1][tid] + s_g[0][2][tid] + s_g[0][3][tid];
                const float g1 = s_g[1][0][tid] + s_g[1][1][tid] + s_g[1][2][tid] + s_g[1][3][tid];
                s_sc[0][tid] = 1.f + 1.f / (1.f + expf(-g0));
                s_sc[1][tid] = 1.f + 1.f / (1.f + expf(-g1));
            }
            __syncthreads();
#pragma unroll
            for (int mt = 0; mt < 2; ++mt) {
                sc[mt][0] = s_sc[0][wm * 32 + mt * 16 + lq];
                sc[mt][1] = s_sc[0][wm * 32 + mt * 16 + lq + 8];
            }
            zero_acc(acc);
        }
        if (j == 23) {                         // switch scales s0 -> s1
#pragma unroll
            for (int mt = 0; mt < 2; ++mt) {
                sc[mt][0] = s_sc[1][wm * 32 + mt * 16 + lq];
                sc[mt][1] = s_sc[1][wm * 32 + mt * 16 + lq + 8];
            }
        }
        __syncthreads();                       // all reads of buf j done
        if (j + 2 < NJOBS) stage(j + 2);
    }

    // epilogue: out = s0*(X0@W1) + s1*(X1@W2) accumulated in acc
#pragma unroll
    for (int mt = 0; mt < 2; ++mt) {
        const int r0 = wm * 32 + mt * 16 + lq;
#pragma unroll
        for (int nt = 0; nt < 8; ++nt) {
            const int cb = wn * 64 + nt * 8 + lr * 2;
            float2 v0 = make_float2(acc[mt][nt][0], acc[mt][nt][1]);
            float2 v1 = make_float2(acc[mt][nt][2], acc[mt][nt][3]);
            *reinterpret_cast<float2*>(out + (rowbase + r0) * DIM + cb) = v0;
            *reinterpret_cast<float2*>(out + (rowbase + r0 + 8) * DIM + cb) = v1;
        }
    }
}

// prep: g_Wt[z][n*GW + k] = tf32_rna(W_z[k][n])
__global__ void wprep_kernel(const float* __restrict__ w1, const float* __restrict__ w2,
                             const float* __restrict__ a1, const float* __restrict__ a2) {
    const int z = blockIdx.x;
    const float* src = (z == 0) ? a1 : (z == 1) ? a2 : (z == 2) ? w1 : w2;
    const int n = threadIdx.x;
    const int k0 = blockIdx.y * 32;
    for (int k = k0; k < k0 + 32; ++k) {
        float v = src[k * DIM + n];
        g_Wt[z][n * GW + k] = __uint_as_float(to_tf32(v));
    }
}

extern "C" void kernel_launch(void* const* d_in, const int* in_sizes, int n_in,
                              void* d_out, int out_size) {
    const float* i0 = (const float*)d_in[0];
    const float* i1 = (const float*)d_in[1];
    const float* W1 = (const float*)d_in[2];
    const float* W2 = (const float*)d_in[3];
    const float* A1 = (const float*)d_in[4];
    const float* A2 = (const float*)d_in[5];
    float* out = (float*)d_out;

    wprep_kernel<<<dim3(4, 8), 256>>>(W1, W2, A1, A2);

    cudaFuncSetAttribute(fused_mma_kernel,
                         cudaFuncAttributeMaxDynamicSharedMemorySize, SMEM_BYTES);
    const int rows = in_sizes[0] / DIM;          // 65536
    fused_mma_kernel<<<rows / TM, THREADS, SMEM_BYTES>>>(i0, i1, out);
    (void)n_in; (void)out_size;
}

// round 9
// speedup vs baseline: 5.0247x; 5.0247x over previous
#include <cuda_runtime.h>
#include <cstdint>
#include <math.h>

#define DIM 256
#define TM 128
#define THREADS 512
#define KC 64
#define NJOBS 16                 // 4 passes x 4 chunks

#define PX 68                    // smem row stride (floats): 68%32==4 -> LDSM conflict-free
#define PW 68
#define GW 256                   // g_Wt gmem row stride
#define XS_FLOATS (TM * PX)      // 8704
#define WS_FLOATS (256 * PW)     // 17408
#define BUF_FLOATS (XS_FLOATS + WS_FLOATS)      // 26112 -> 104448 B
#define BUF_BYTES (BUF_FLOATS * 4)
#define SMEM_BYTES (2 * BUF_BYTES)              // 208896 B -> 1 CTA/SM, 16 warps

__device__ float g_Wt[4][256 * GW];   // [n][k], transposed + tf32-rna-rounded

__device__ __forceinline__ uint32_t smem_u32(const void* p) {
    uint32_t a;
    asm("{ .reg .u64 t; cvta.to.shared.u64 t, %1; cvt.u32.u64 %0, t; }" : "=r"(a) : "l"(p));
    return a;
}
__device__ __forceinline__ void cp16(uint32_t s, const float* g) {
    asm volatile("cp.async.cg.shared.global [%0], [%1], 16;" :: "r"(s), "l"(g));
}
#define CP_COMMIT() asm volatile("cp.async.commit_group;" ::: "memory")
#define CP_WAIT(n)  asm volatile("cp.async.wait_group %0;" :: "n"(n) : "memory")

__device__ __forceinline__ uint32_t to_tf32(float x) {
    uint32_t r;
    asm("cvt.rna.tf32.f32 %0, %1;" : "=r"(r) : "f"(x));
    return r;
}
__device__ __forceinline__ void ldsm4(uint32_t* r, uint32_t addr) {
    asm volatile("ldmatrix.sync.aligned.m8n8.x4.shared.b16 {%0,%1,%2,%3}, [%4];"
                 : "=r"(r[0]), "=r"(r[1]), "=r"(r[2]), "=r"(r[3]) : "r"(addr));
}
__device__ __forceinline__ void mma8(float* c, const uint32_t* a, const uint32_t* b) {
    asm volatile(
        "mma.sync.aligned.m16n8k8.row.col.f32.tf32.tf32.f32 "
        "{%0,%1,%2,%3}, {%4,%5,%6,%7}, {%8,%9}, {%0,%1,%2,%3};"
        : "+f"(c[0]), "+f"(c[1]), "+f"(c[2]), "+f"(c[3])
        : "r"(a[0]), "r"(a[1]), "r"(a[2]), "r"(a[3]), "r"(b[0]), "r"(b[1]));
}

// ---- one KC=64 chunk: acc(32x64 warptile) += X @ W ----  (all indices STATIC)
template <bool SCALE>
__device__ __forceinline__ void gemm_chunk(uint32_t a_base, uint32_t b_base,
                                           float (&acc)[2][8][4],
                                           const float (&sc)[2][2]) {
#pragma unroll
    for (int ks = 0; ks < 8; ++ks) {
        uint32_t ua[2][4];
        ldsm4(ua[0], a_base + ks * 32);
        ldsm4(ua[1], a_base + 16 * PX * 4 + ks * 32);
        if (SCALE) {
#pragma unroll
            for (int mt = 0; mt < 2; ++mt) {
                ua[mt][0] = __float_as_uint(__uint_as_float(ua[mt][0]) * sc[mt][0]);
                ua[mt][1] = __float_as_uint(__uint_as_float(ua[mt][1]) * sc[mt][1]);
                ua[mt][2] = __float_as_uint(__uint_as_float(ua[mt][2]) * sc[mt][0]);
                ua[mt][3] = __float_as_uint(__uint_as_float(ua[mt][3]) * sc[mt][1]);
            }
        }
#pragma unroll
        for (int nt2 = 0; nt2 < 4; ++nt2) {
            uint32_t b[4];                         // nt = 2*nt2, 2*nt2+1
            ldsm4(b, b_base + nt2 * (16 * PW * 4) + ks * 32);
            mma8(acc[0][2 * nt2],     ua[0], b);
            mma8(acc[1][2 * nt2],     ua[1], b);
            mma8(acc[0][2 * nt2 + 1], ua[0], b + 2);
            mma8(acc[1][2 * nt2 + 1], ua[1], b + 2);
        }
    }
}

__device__ __forceinline__ void zero_acc(float (&acc)[2][8][4]) {
#pragma unroll
    for (int mt = 0; mt < 2; ++mt)
#pragma unroll
        for (int nt = 0; nt < 8; ++nt)
#pragma unroll
            for (int q = 0; q < 4; ++q) acc[mt][nt][q] = 0.f;
}

__device__ __forceinline__ void gate_dot(const float* __restrict__ Xo,
                                         const float (&acc)[2][8][4], int g,
                                         int wm, int wn, int lq, int lr,
                                         float (*s_g)[4][TM]) {
    float pr[2][2] = {{0.f, 0.f}, {0.f, 0.f}};
#pragma unroll
    for (int mt = 0; mt < 2; ++mt) {
        const int r0 = wm * 32 + mt * 16 + lq;
#pragma unroll
        for (int nt = 0; nt < 8; ++nt) {
            const int cb = wn * 64 + nt * 8 + lr * 2;
            float2 v0 = *reinterpret_cast<const float2*>(Xo + (size_t)r0 * DIM + cb);
            float2 v1 = *reinterpret_cast<const float2*>(Xo + (size_t)(r0 + 8) * DIM + cb);
            pr[mt][0] += acc[mt][nt][0] * v0.x + acc[mt][nt][1] * v0.y;
            pr[mt][1] += acc[mt][nt][2] * v1.x + acc[mt][nt][3] * v1.y;
        }
    }
#pragma unroll
    for (int off = 1; off <= 2; off <<= 1)
#pragma unroll
        for (int mt = 0; mt < 2; ++mt) {
            pr[mt][0] += __shfl_xor_sync(0xFFFFFFFFu, pr[mt][0], off);
            pr[mt][1] += __shfl_xor_sync(0xFFFFFFFFu, pr[mt][1], off);
        }
    if (lr == 0) {
#pragma unroll
        for (int mt = 0; mt < 2; ++mt) {
            s_g[g][wn][wm * 32 + mt * 16 + lq] = pr[mt][0];
            s_g[g][wn][wm * 32 + mt * 16 + lq + 8] = pr[mt][1];
        }
    }
}

__global__ void __launch_bounds__(THREADS, 1)
fused_mma_kernel(const float* __restrict__ i0, const float* __restrict__ i1,
                 float* __restrict__ out) {
    extern __shared__ float dyn[];
    __shared__ float s_g[2][4][TM];
    __shared__ float s_sc[2][TM];

    const int tid = threadIdx.x;
    const int l = tid & 31, w = tid >> 5;
    const int wm = w >> 2, wn = w & 3;         // 4m x 4n warp grid
    const int lq = l >> 2, lr = l & 3;
    const size_t rowbase = (size_t)blockIdx.x * TM;
    const float* X0g = i0 + rowbase * DIM;
    const float* X1g = i1 + rowbase * DIM;
    const uint32_t sb = smem_u32(dyn);

    // per-lane LDSM addressing
    const int arow = ((l >> 3) & 1) * 8 + (l & 7);
    const int acg  = (l >> 4) & 1;
    const int brow = ((l >> 4) & 1) * 8 + (l & 7);
    const int bcg  = (l >> 3) & 1;
    const uint32_t a_off = (uint32_t)((wm * 32 + arow) * PX + acg * 4) * 4;
    const uint32_t b_off = (uint32_t)(XS_FLOATS + (wn * 64 + brow) * PW + bcg * 4) * 4;

    // jobs 0..15: pass p=j>>2, chunk c=j&3
    //  p0: A=X1,B=attn1 -> g0 dot X0    p1: A=X0,B=attn2 -> g1 dot X1
    //  p2: A=X0,B=W1 (scale s0)         p3: A=X1,B=W2 (scale s1)
    auto stage = [&](int j) {
        const int p = j >> 2, c = j & 3;
        const float* As = (p == 0 || p == 3) ? X1g : X0g;
        const float* Bs = g_Wt[p];
        const uint32_t base = sb + (uint32_t)(j & 1) * BUF_BYTES;
#pragma unroll
        for (int t = 0; t < 4; ++t) {          // X chunk: 128 x 64
            const int id = tid + t * THREADS;
            const int r = id >> 4, c4 = (id & 15) << 2;
            cp16(base + (uint32_t)(r * PX + c4) * 4, As + (size_t)r * DIM + c * 64 + c4);
        }
#pragma unroll
        for (int t = 0; t < 8; ++t) {          // Wt chunk: 256 n x 64 k
            const int id = tid + t * THREADS;
            const int n = id >> 4, k4 = (id & 15) << 2;
            cp16(base + (uint32_t)(XS_FLOATS + n * PW + k4) * 4,
                 Bs + (size_t)n * GW + c * 64 + k4);
        }
        CP_COMMIT();
    };

    float acc[2][8][4];
    zero_acc(acc);
    float sc[2][2] = {{1.f, 1.f}, {1.f, 1.f}};

    stage(0);
    stage(1);

    for (int j = 0; j < NJOBS; ++j) {
        if (j == NJOBS - 1) { CP_WAIT(0); } else { CP_WAIT(1); }
        __syncthreads();
        const uint32_t base = sb + (uint32_t)(j & 1) * BUF_BYTES;
        if (j >= 8) gemm_chunk<true>(base + a_off, base + b_off, acc, sc);
        else        gemm_chunk<false>(base + a_off, base + b_off, acc, sc);

        if (j == 3) {                          // g0 = rowdot(U0, X0)
            gate_dot(X0g, acc, 0, wm, wn, lq, lr, s_g);
            zero_acc(acc);
        }
        if (j == 7) {                          // g1; sigmoid; load s0 scales
            gate_dot(X1g, acc, 1, wm, wn, lq, lr, s_g);
            __syncthreads();
            if (tid < TM) {
                const float g0 = s_g[0][0][tid] + s_g[0][1][tid] + s_g[0][2][tid] + s_g[0][3][tid];
                const float g1 = s_g[1][0][tid] + s_g[1][1][tid] + s_g[1][2][tid] + s_g[1][3][tid];
                s_sc[0][tid] = 1.f + 1.f / (1.f + expf(-g0));
                s_sc[1][tid] = 1.f + 1.f / (1.f + expf(-g1));
            }
            __syncthreads();
#pragma unroll
            for (int mt = 0; mt < 2; ++mt) {
                sc[mt][0] = s_sc[0][wm * 32 + mt * 16 + lq];
                sc[mt][1] = s_sc[0][wm * 32 + mt * 16 + lq + 8];
            }
            zero_acc(acc);
        }
        if (j == 11) {                         // switch scales s0 -> s1
#pragma unroll
            for (int mt = 0; mt < 2; ++mt) {
                sc[mt][0] = s_sc[1][wm * 32 + mt * 16 + lq];
                sc[mt][1] = s_sc[1][wm * 32 + mt * 16 + lq + 8];
            }
        }
        __syncthreads();                       // all reads of buf j done
        if (j + 2 < NJOBS) stage(j + 2);
    }

    // epilogue: out = s0*(X0@W1) + s1*(X1@W2) accumulated in acc
#pragma unroll
    for (int mt = 0; mt < 2; ++mt) {
        const int r0 = wm * 32 + mt * 16 + lq;
#pragma unroll
        for (int nt = 0; nt < 8; ++nt) {
            const int cb = wn * 64 + nt * 8 + lr * 2;
            float2 v0 = make_float2(acc[mt][nt][0], acc[mt][nt][1]);
            float2 v1 = make_float2(acc[mt][nt][2], acc[mt][nt][3]);
            *reinterpret_cast<float2*>(out + (rowbase + r0) * DIM + cb) = v0;
            *reinterpret_cast<float2*>(out + (rowbase + r0 + 8) * DIM + cb) = v1;
        }
    }
}

// prep: g_Wt[z][n*GW + k] = tf32_rna(W_z[k][n])
__global__ void wprep_kernel(const float* __restrict__ w1, const float* __restrict__ w2,
                             const float* __restrict__ a1, const float* __restrict__ a2) {
    const int z = blockIdx.x;
    const float* src = (z == 0) ? a1 : (z == 1) ? a2 : (z == 2) ? w1 : w2;
    const int n = threadIdx.x;
    const int k0 = blockIdx.y * 32;
    for (int k = k0; k < k0 + 32; ++k) {
        float v = src[k * DIM + n];
        g_Wt[z][n * GW + k] = __uint_as_float(to_tf32(v));
    }
}

extern "C" void kernel_launch(void* const* d_in, const int* in_sizes, int n_in,
                              void* d_out, int out_size) {
    const float* i0 = (const float*)d_in[0];
    const float* i1 = (const float*)d_in[1];
    const float* W1 = (const float*)d_in[2];
    const float* W2 = (const float*)d_in[3];
    const float* A1 = (const float*)d_in[4];
    const float* A2 = (const float*)d_in[5];
    float* out = (float*)d_out;

    wprep_kernel<<<dim3(4, 8), 256>>>(W1, W2, A1, A2);

    cudaFuncSetAttribute(fused_mma_kernel,
                         cudaFuncAttributeMaxDynamicSharedMemorySize, SMEM_BYTES);
    const int rows = in_sizes[0] / DIM;          // 65536
    fused_mma_kernel<<<rows / TM, THREADS, SMEM_BYTES>>>(i0, i1, out);
    (void)n_in; (void)out_size;
}

// round 10
// speedup vs baseline: 5.7412x; 1.1426x over previous
#include <cuda_runtime.h>
#include <cstdint>
#include <math.h>

#define DIM 256
#define TM 64
#define THREADS 256
#define KC 32
#define NJOBS 32                 // 4 passes x 8 chunks

#define PX 36                    // smem row stride (floats): 36%32==4 -> LDSM conflict-free
#define PW 36
#define GW 256                   // g_Wt gmem row stride
#define XS_FLOATS (TM * PX)      // 2304
#define WS_FLOATS (256 * PW)     // 9216
#define BUF_FLOATS (XS_FLOATS + WS_FLOATS)      // 11520 -> 46080 B
#define BUF_BYTES (BUF_FLOATS * 4)
#define SMEM_BYTES (2 * BUF_BYTES)              // 92160 B -> 2 CTAs/SM

__device__ float g_Wt[4][256 * GW];   // [n][k], transposed + tf32-rna-rounded

__device__ __forceinline__ uint32_t smem_u32(const void* p) {
    uint32_t a;
    asm("{ .reg .u64 t; cvta.to.shared.u64 t, %1; cvt.u32.u64 %0, t; }" : "=r"(a) : "l"(p));
    return a;
}
__device__ __forceinline__ void cp16(uint32_t s, const float* g) {
    asm volatile("cp.async.cg.shared.global [%0], [%1], 16;" :: "r"(s), "l"(g));
}
#define CP_COMMIT() asm volatile("cp.async.commit_group;" ::: "memory")
#define CP_WAIT(n)  asm volatile("cp.async.wait_group %0;" :: "n"(n) : "memory")

__device__ __forceinline__ uint32_t to_tf32(float x) {
    uint32_t r;
    asm("cvt.rna.tf32.f32 %0, %1;" : "=r"(r) : "f"(x));
    return r;
}
__device__ __forceinline__ void ldsm4(uint32_t* r, uint32_t addr) {
    asm volatile("ldmatrix.sync.aligned.m8n8.x4.shared.b16 {%0,%1,%2,%3}, [%4];"
                 : "=r"(r[0]), "=r"(r[1]), "=r"(r[2]), "=r"(r[3]) : "r"(addr));
}
__device__ __forceinline__ void mma8(float* c, const uint32_t* a, const uint32_t* b) {
    asm volatile(
        "mma.sync.aligned.m16n8k8.row.col.f32.tf32.tf32.f32 "
        "{%0,%1,%2,%3}, {%4,%5,%6,%7}, {%8,%9}, {%0,%1,%2,%3};"
        : "+f"(c[0]), "+f"(c[1]), "+f"(c[2]), "+f"(c[3])
        : "r"(a[0]), "r"(a[1]), "r"(a[2]), "r"(a[3]), "r"(b[0]), "r"(b[1]));
}

// ---- one KC=32 chunk: acc(32x64 warptile) += X @ W ----
// KROT: compile-time per-warp k-step rotation (de-phasing). All indices static.
template <bool SCALE, int KROT>
__device__ __forceinline__ void gemm_chunk(uint32_t a_base, uint32_t b_base,
                                           float (&acc)[2][8][4],
                                           const float (&sc)[2][2]) {
#pragma unroll
    for (int kk = 0; kk < 4; ++kk) {
        constexpr int KR = KROT;               // keep constexpr through unroll
        const int ks = (kk + KR) & 3;          // compile-time per unrolled kk
        uint32_t ua[2][4];
        ldsm4(ua[0], a_base + ks * 32);
        ldsm4(ua[1], a_base + 16 * PX * 4 + ks * 32);
        if (SCALE) {
#pragma unroll
            for (int mt = 0; mt < 2; ++mt) {
                ua[mt][0] = __float_as_uint(__uint_as_float(ua[mt][0]) * sc[mt][0]);
                ua[mt][1] = __float_as_uint(__uint_as_float(ua[mt][1]) * sc[mt][1]);
                ua[mt][2] = __float_as_uint(__uint_as_float(ua[mt][2]) * sc[mt][0]);
                ua[mt][3] = __float_as_uint(__uint_as_float(ua[mt][3]) * sc[mt][1]);
            }
        }
#pragma unroll
        for (int nt2 = 0; nt2 < 4; ++nt2) {
            uint32_t b[4];                     // nt = 2*nt2, 2*nt2+1 (STATIC)
            ldsm4(b, b_base + nt2 * (16 * PW * 4) + ks * 32);
            mma8(acc[0][2 * nt2],     ua[0], b);
            mma8(acc[1][2 * nt2],     ua[1], b);
            mma8(acc[0][2 * nt2 + 1], ua[0], b + 2);
            mma8(acc[1][2 * nt2 + 1], ua[1], b + 2);
        }
    }
}

template <bool SCALE>
__device__ __forceinline__ void gemm_dispatch(uint32_t a_base, uint32_t b_base,
                                              float (&acc)[2][8][4],
                                              const float (&sc)[2][2], int krot) {
    switch (krot) {                             // warp-uniform branch
        case 0: gemm_chunk<SCALE, 0>(a_base, b_base, acc, sc); break;
        case 1: gemm_chunk<SCALE, 1>(a_base, b_base, acc, sc); break;
        case 2: gemm_chunk<SCALE, 2>(a_base, b_base, acc, sc); break;
        default: gemm_chunk<SCALE, 3>(a_base, b_base, acc, sc); break;
    }
}

__device__ __forceinline__ void zero_acc(float (&acc)[2][8][4]) {
#pragma unroll
    for (int mt = 0; mt < 2; ++mt)
#pragma unroll
        for (int nt = 0; nt < 8; ++nt)
#pragma unroll
            for (int q = 0; q < 4; ++q) acc[mt][nt][q] = 0.f;
}

__device__ __forceinline__ void gate_dot(const float* __restrict__ Xo,
                                         const float (&acc)[2][8][4], int g,
                                         int wm, int wn, int lq, int lr,
                                         float (*s_g)[4][TM]) {
    float pr[2][2] = {{0.f, 0.f}, {0.f, 0.f}};
#pragma unroll
    for (int mt = 0; mt < 2; ++mt) {
        const int r0 = wm * 32 + mt * 16 + lq;
#pragma unroll
        for (int nt = 0; nt < 8; ++nt) {
            const int cb = wn * 64 + nt * 8 + lr * 2;
            float2 v0 = *reinterpret_cast<const float2*>(Xo + (size_t)r0 * DIM + cb);
            float2 v1 = *reinterpret_cast<const float2*>(Xo + (size_t)(r0 + 8) * DIM + cb);
            pr[mt][0] += acc[mt][nt][0] * v0.x + acc[mt][nt][1] * v0.y;
            pr[mt][1] += acc[mt][nt][2] * v1.x + acc[mt][nt][3] * v1.y;
        }
    }
#pragma unroll
    for (int off = 1; off <= 2; off <<= 1)
#pragma unroll
        for (int mt = 0; mt < 2; ++mt) {
            pr[mt][0] += __shfl_xor_sync(0xFFFFFFFFu, pr[mt][0], off);
            pr[mt][1] += __shfl_xor_sync(0xFFFFFFFFu, pr[mt][1], off);
        }
    if (lr == 0) {
#pragma unroll
        for (int mt = 0; mt < 2; ++mt) {
            s_g[g][wn][wm * 32 + mt * 16 + lq] = pr[mt][0];
            s_g[g][wn][wm * 32 + mt * 16 + lq + 8] = pr[mt][1];
        }
    }
}

__global__ void __launch_bounds__(THREADS, 2)
fused_mma_kernel(const float* __restrict__ i0, const float* __restrict__ i1,
                 float* __restrict__ out) {
    extern __shared__ float dyn[];
    __shared__ float s_g[2][4][TM];
    __shared__ float s_sc[2][TM];

    const int tid = threadIdx.x;
    const int l = tid & 31, w = tid >> 5;
    const int wm = w >> 2, wn = w & 3;         // m-split 2, n-split 4
    const int lq = l >> 2, lr = l & 3;
    const int krot = w & 3;                    // de-phase k-steps across warps
    const size_t rowbase = (size_t)blockIdx.x * TM;
    const float* X0g = i0 + rowbase * DIM;
    const float* X1g = i1 + rowbase * DIM;
    const uint32_t sb = smem_u32(dyn);

    // per-lane LDSM addressing
    const int arow = ((l >> 3) & 1) * 8 + (l & 7);
    const int acg  = (l >> 4) & 1;
    const int brow = ((l >> 4) & 1) * 8 + (l & 7);
    const int bcg  = (l >> 3) & 1;
    const uint32_t a_off = (uint32_t)((wm * 32 + arow) * PX + acg * 4) * 4;
    const uint32_t b_off = (uint32_t)(XS_FLOATS + (wn * 64 + brow) * PW + bcg * 4) * 4;

    // jobs 0..31: pass p=j>>3, chunk c=j&7
    //  p0: A=X1,B=attn1 -> g0 dot X0    p1: A=X0,B=attn2 -> g1 dot X1
    //  p2: A=X0,B=W1 (scale s0)         p3: A=X1,B=W2 (scale s1)
    auto stage = [&](int j) {
        const int p = j >> 3, c = j & 7;
        const float* As = (p == 0 || p == 3) ? X1g : X0g;
        const float* Bs = g_Wt[p];
        const uint32_t base = sb + (uint32_t)(j & 1) * BUF_BYTES;
#pragma unroll
        for (int t = 0; t < 2; ++t) {          // X chunk: 64 x 32
            const int id = tid + t * THREADS;
            const int r = id >> 3, c4 = (id & 7) << 2;
            cp16(base + (uint32_t)(r * PX + c4) * 4, As + (size_t)r * DIM + c * 32 + c4);
        }
#pragma unroll
        for (int t = 0; t < 8; ++t) {          // Wt chunk: 256 n x 32 k
            const int id = tid + t * THREADS;
            const int n = id >> 3, k4 = (id & 7) << 2;
            cp16(base + (uint32_t)(XS_FLOATS + n * PW + k4) * 4,
                 Bs + (size_t)n * GW + c * 32 + k4);
        }
        CP_COMMIT();
    };

    float acc[2][8][4];
    zero_acc(acc);
    float sc[2][2] = {{1.f, 1.f}, {1.f, 1.f}};

    stage(0);
    stage(1);

    for (int j = 0; j < NJOBS; ++j) {
        if (j == NJOBS - 1) { CP_WAIT(0); } else { CP_WAIT(1); }
        __syncthreads();
        const uint32_t base = sb + (uint32_t)(j & 1) * BUF_BYTES;
        if (j >= 16) gemm_dispatch<true>(base + a_off, base + b_off, acc, sc, krot);
        else         gemm_dispatch<false>(base + a_off, base + b_off, acc, sc, krot);

        if (j == 7) {                          // g0 = rowdot(U0, X0)
            gate_dot(X0g, acc, 0, wm, wn, lq, lr, s_g);
            zero_acc(acc);
        }
        if (j == 15) {                         // g1; sigmoid; load s0 scales
            gate_dot(X1g, acc, 1, wm, wn, lq, lr, s_g);
            __syncthreads();
            if (tid < TM) {
                const float g0 = s_g[0][0][tid] + s_g[0][1][tid] + s_g[0][2][tid] + s_g[0][3][tid];
                const float g1 = s_g[1][0][tid] + s_g[1][1][tid] + s_g[1][2][tid] + s_g[1][3][tid];
                s_sc[0][tid] = 1.f + 1.f / (1.f + expf(-g0));
                s_sc[1][tid] = 1.f + 1.f / (1.f + expf(-g1));
            }
            __syncthreads();
#pragma unroll
            for (int mt = 0; mt < 2; ++mt) {
                sc[mt][0] = s_sc[0][wm * 32 + mt * 16 + lq];
                sc[mt][1] = s_sc[0][wm * 32 + mt * 16 + lq + 8];
            }
            zero_acc(acc);
        }
        if (j == 23) {                         // switch scales s0 -> s1
#pragma unroll
            for (int mt = 0; mt < 2; ++mt) {
                sc[mt][0] = s_sc[1][wm * 32 + mt * 16 + lq];
                sc[mt][1] = s_sc[1][wm * 32 + mt * 16 + lq + 8];
            }
        }
        __syncthreads();                       // all reads of buf j done
        if (j + 2 < NJOBS) stage(j + 2);
    }

    // epilogue: out = s0*(X0@W1) + s1*(X1@W2) accumulated in acc
#pragma unroll
    for (int mt = 0; mt < 2; ++mt) {
        const int r0 = wm * 32 + mt * 16 + lq;
#pragma unroll
        for (int nt = 0; nt < 8; ++nt) {
            const int cb = wn * 64 + nt * 8 + lr * 2;
            float2 v0 = make_float2(acc[mt][nt][0], acc[mt][nt][1]);
            float2 v1 = make_float2(acc[mt][nt][2], acc[mt][nt][3]);
            *reinterpret_cast<float2*>(out + (rowbase + r0) * DIM + cb) = v0;
            *reinterpret_cast<float2*>(out + (rowbase + r0 + 8) * DIM + cb) = v1;
        }
    }
}

// prep: g_Wt[z][n*GW + k] = tf32_rna(W_z[k][n])
__global__ void wprep_kernel(const float* __restrict__ w1, const float* __restrict__ w2,
                             const float* __restrict__ a1, const float* __restrict__ a2) {
    const int z = blockIdx.x;
    const float* src = (z == 0) ? a1 : (z == 1) ? a2 : (z == 2) ? w1 : w2;
    const int n = threadIdx.x;
    const int k0 = blockIdx.y * 32;
    for (int k = k0; k < k0 + 32; ++k) {
        float v = src[k * DIM + n];
        g_Wt[z][n * GW + k] = __uint_as_float(to_tf32(v));
    }
}

extern "C" void kernel_launch(void* const* d_in, const int* in_sizes, int n_in,
                              void* d_out, int out_size) {
    const float* i0 = (const float*)d_in[0];
    const float* i1 = (const float*)d_in[1];
    const float* W1 = (const float*)d_in[2];
    const float* W2 = (const float*)d_in[3];
    const float* A1 = (const float*)d_in[4];
    const float* A2 = (const float*)d_in[5];
    float* out = (float*)d_out;

    wprep_kernel<<<dim3(4, 8), 256>>>(W1, W2, A1, A2);

    cudaFuncSetAttribute(fused_mma_kernel,
                         cudaFuncAttributeMaxDynamicSharedMemorySize, SMEM_BYTES);
    const int rows = in_sizes[0] / DIM;          // 65536
    fused_mma_kernel<<<rows / TM, THREADS, SMEM_BYTES>>>(i0, i1, out);
    (void)n_in; (void)out_size;
}

// round 11
// speedup vs baseline: 7.9974x; 1.3930x over previous
#include <cuda_runtime.h>
#include <cuda_fp16.h>
#include <cstdint>
#include <math.h>

#define DIM 256
#define TM 64
#define THREADS 256
#define NJOBS 16                  // 4 passes x 4 chunks (KC=64)

#define PXB 144                   // smem row stride BYTES (72 fp16): 16r mod 128 bijective
#define XS_BYTES (TM * PXB)       // 9216
#define WS_BYTES (256 * PXB)      // 36864
#define BUF_BYTES (XS_BYTES + WS_BYTES)   // 46080
#define SMEM_BYTES (2 * BUF_BYTES)        // 92160 -> 2 CTAs/SM

#define NROWS 16777216            // 4*32*512*256

__device__ __half g_X[2][NROWS];  // fp16 copies of i0, i1
__device__ __half g_W[4][DIM * DIM];   // [n][k] transposed fp16: attn1, attn2, W1, W2

__device__ __forceinline__ uint32_t smem_u32(const void* p) {
    uint32_t a;
    asm("{ .reg .u64 t; cvta.to.shared.u64 t, %1; cvt.u32.u64 %0, t; }" : "=r"(a) : "l"(p));
    return a;
}
__device__ __forceinline__ void cp16(uint32_t s, const void* g) {
    asm volatile("cp.async.cg.shared.global [%0], [%1], 16;" :: "r"(s), "l"(g));
}
#define CP_COMMIT() asm volatile("cp.async.commit_group;" ::: "memory")
#define CP_WAIT(n)  asm volatile("cp.async.wait_group %0;" :: "n"(n) : "memory")

__device__ __forceinline__ void ldsm4(uint32_t* r, uint32_t addr) {
    asm volatile("ldmatrix.sync.aligned.m8n8.x4.shared.b16 {%0,%1,%2,%3}, [%4];"
                 : "=r"(r[0]), "=r"(r[1]), "=r"(r[2]), "=r"(r[3]) : "r"(addr));
}
__device__ __forceinline__ void mma16(float* c, const uint32_t* a, const uint32_t* b) {
    asm volatile(
        "mma.sync.aligned.m16n8k16.row.col.f32.f16.f16.f32 "
        "{%0,%1,%2,%3}, {%4,%5,%6,%7}, {%8,%9}, {%0,%1,%2,%3};"
        : "+f"(c[0]), "+f"(c[1]), "+f"(c[2]), "+f"(c[3])
        : "r"(a[0]), "r"(a[1]), "r"(a[2]), "r"(a[3]), "r"(b[0]), "r"(b[1]));
}

// ---- one KC=64 chunk: acc(32x64 warptile) += X @ W, fp16 k16 steps ----
__device__ __forceinline__ void gemm_chunk(uint32_t a_base, uint32_t b_base,
                                           float (&acc)[2][8][4]) {
#pragma unroll
    for (int ks = 0; ks < 4; ++ks) {              // k16 steps
        uint32_t ua[2][4];
        ldsm4(ua[0], a_base + ks * 32);
        ldsm4(ua[1], a_base + 16 * PXB + ks * 32);
#pragma unroll
        for (int nt2 = 0; nt2 < 4; ++nt2) {       // 16 n-rows per ldsm.x4
            uint32_t b[4];
            ldsm4(b, b_base + nt2 * (16 * PXB) + ks * 32);
            mma16(acc[0][2 * nt2],     ua[0], b);
            mma16(acc[1][2 * nt2],     ua[1], b);
            mma16(acc[0][2 * nt2 + 1], ua[0], b + 2);
            mma16(acc[1][2 * nt2 + 1], ua[1], b + 2);
        }
    }
}

__device__ __forceinline__ void zero_acc(float (&acc)[2][8][4]) {
#pragma unroll
    for (int mt = 0; mt < 2; ++mt)
#pragma unroll
        for (int nt = 0; nt < 8; ++nt)
#pragma unroll
            for (int q = 0; q < 4; ++q) acc[mt][nt][q] = 0.f;
}

__device__ __forceinline__ void gate_dot(const float* __restrict__ Xo,
                                         const float (&acc)[2][8][4], int g,
                                         int wm, int wn, int lq, int lr,
                                         float (*s_g)[4][TM]) {
    float pr[2][2] = {{0.f, 0.f}, {0.f, 0.f}};
#pragma unroll
    for (int mt = 0; mt < 2; ++mt) {
        const int r0 = wm * 32 + mt * 16 + lq;
#pragma unroll
        for (int nt = 0; nt < 8; ++nt) {
            const int cb = wn * 64 + nt * 8 + lr * 2;
            float2 v0 = *reinterpret_cast<const float2*>(Xo + (size_t)r0 * DIM + cb);
            float2 v1 = *reinterpret_cast<const float2*>(Xo + (size_t)(r0 + 8) * DIM + cb);
            pr[mt][0] += acc[mt][nt][0] * v0.x + acc[mt][nt][1] * v0.y;
            pr[mt][1] += acc[mt][nt][2] * v1.x + acc[mt][nt][3] * v1.y;
        }
    }
#pragma unroll
    for (int off = 1; off <= 2; off <<= 1)
#pragma unroll
        for (int mt = 0; mt < 2; ++mt) {
            pr[mt][0] += __shfl_xor_sync(0xFFFFFFFFu, pr[mt][0], off);
            pr[mt][1] += __shfl_xor_sync(0xFFFFFFFFu, pr[mt][1], off);
        }
    if (lr == 0) {
#pragma unroll
        for (int mt = 0; mt < 2; ++mt) {
            s_g[g][wn][wm * 32 + mt * 16 + lq] = pr[mt][0];
            s_g[g][wn][wm * 32 + mt * 16 + lq + 8] = pr[mt][1];
        }
    }
}

__global__ void __launch_bounds__(THREADS, 2)
fused_mma_kernel(const float* __restrict__ i0, const float* __restrict__ i1,
                 float* __restrict__ out) {
    extern __shared__ char dyn[];
    __shared__ float s_g[2][4][TM];
    __shared__ float s_sc[2][TM];

    const int tid = threadIdx.x;
    const int l = tid & 31, w = tid >> 5;
    const int wm = w >> 2, wn = w & 3;            // m-split 2, n-split 4
    const int lq = l >> 2, lr = l & 3;
    const size_t rowbase = (size_t)blockIdx.x * TM;
    const float* X0g = i0 + rowbase * DIM;
    const float* X1g = i1 + rowbase * DIM;
    const uint32_t sb = smem_u32(dyn);

    // per-lane ldsm addressing (canonical fp16 recipes)
    // A (rows x k): matrix m = l>>3: row += (m&1)*8, k-half = m>>1
    const uint32_t a_off = (uint32_t)(wm * 32 + (l & 7) + ((l >> 3) & 1) * 8) * PXB
                         + (uint32_t)((l >> 4) & 1) * 16;
    // B ([n][k] rows): matrix m: n-octet = m>>1, k-half = m&1
    const uint32_t b_off = XS_BYTES
                         + (uint32_t)(wn * 64 + ((l >> 4) & 1) * 8 + (l & 7)) * PXB
                         + (uint32_t)((l >> 3) & 1) * 16;

    // jobs 0..15: pass p=j>>2, chunk c=j&3 (KC=64)
    //  p0: A=X1h,B=attn1 -> g0 dot X0   p1: A=X0h,B=attn2 -> g1 dot X1
    //  p2: A=X0h,B=W1 (raw)             p3: A=X1h,B=W2 (raw; acc rescaled)
    auto stage = [&](int j) {
        const int p = j >> 2, c = j & 3;
        const __half* As = g_X[(p == 0 || p == 3) ? 1 : 0] + rowbase * DIM;
        const __half* Bs = g_W[p];
        const uint32_t base = sb + (uint32_t)(j & 1) * BUF_BYTES;
#pragma unroll
        for (int t = 0; t < 2; ++t) {             // X chunk: 64 rows x 64 fp16
            const int id = tid + t * THREADS;
            const int r = id >> 3, gk = id & 7;
            cp16(base + (uint32_t)(r * PXB + gk * 16), As + r * DIM + c * 64 + gk * 8);
        }
#pragma unroll
        for (int t = 0; t < 8; ++t) {             // W chunk: 256 n x 64 k fp16
            const int id = tid + t * THREADS;
            const int n = id >> 3, gk = id & 7;
            cp16(base + (uint32_t)(XS_BYTES + n * PXB + gk * 16),
                 Bs + n * DIM + c * 64 + gk * 8);
        }
        CP_COMMIT();
    };

    float acc[2][8][4];
    zero_acc(acc);

    stage(0);
    stage(1);

    for (int j = 0; j < NJOBS; ++j) {
        if (j == NJOBS - 1) { CP_WAIT(0); } else { CP_WAIT(1); }
        __syncthreads();
        const uint32_t base = sb + (uint32_t)(j & 1) * BUF_BYTES;
        gemm_chunk(base + a_off, base + b_off, acc);

        if (j == 3) {                             // g0 = rowdot(U0, X0)
            gate_dot(X0g, acc, 0, wm, wn, lq, lr, s_g);
            zero_acc(acc);
        }
        if (j == 7) {                             // g1; sigmoid -> s0, s1
            gate_dot(X1g, acc, 1, wm, wn, lq, lr, s_g);
            __syncthreads();
            if (tid < TM) {
                const float g0 = s_g[0][0][tid] + s_g[0][1][tid] + s_g[0][2][tid] + s_g[0][3][tid];
                const float g1 = s_g[1][0][tid] + s_g[1][1][tid] + s_g[1][2][tid] + s_g[1][3][tid];
                s_sc[0][tid] = 1.f + 1.f / (1.f + expf(-g0));
                s_sc[1][tid] = 1.f + 1.f / (1.f + expf(-g1));
            }
            __syncthreads();
            zero_acc(acc);
        }
        if (j == 11) {                            // acc = P0 -> scale by s0/s1 (fp32 exact)
#pragma unroll
            for (int mt = 0; mt < 2; ++mt) {
                const int r0 = wm * 32 + mt * 16 + lq;
                const float rt0 = s_sc[0][r0] / s_sc[1][r0];
                const float rt1 = s_sc[0][r0 + 8] / s_sc[1][r0 + 8];
#pragma unroll
                for (int nt = 0; nt < 8; ++nt) {
                    acc[mt][nt][0] *= rt0; acc[mt][nt][1] *= rt0;
                    acc[mt][nt][2] *= rt1; acc[mt][nt][3] *= rt1;
                }
            }
        }
        __syncthreads();                          // all reads of buf j done
        if (j + 2 < NJOBS) stage(j + 2);
    }

    // epilogue: out = s1 * acc = s0*P0 + s1*P1
#pragma unroll
    for (int mt = 0; mt < 2; ++mt) {
        const int r0 = wm * 32 + mt * 16 + lq;
        const float f0 = s_sc[1][r0];
        const float f1 = s_sc[1][r0 + 8];
#pragma unroll
        for (int nt = 0; nt < 8; ++nt) {
            const int cb = wn * 64 + nt * 8 + lr * 2;
            float2 v0 = make_float2(acc[mt][nt][0] * f0, acc[mt][nt][1] * f0);
            float2 v1 = make_float2(acc[mt][nt][2] * f1, acc[mt][nt][3] * f1);
            *reinterpret_cast<float2*>(out + (rowbase + r0) * DIM + cb) = v0;
            *reinterpret_cast<float2*>(out + (rowbase + r0 + 8) * DIM + cb) = v1;
        }
    }
}

// ---- prep: inputs fp32 -> fp16 ----
__global__ void xprep_kernel(const float* __restrict__ i0, const float* __restrict__ i1) {
    const float* src = blockIdx.y ? i1 : i0;
    __half* dst = g_X[blockIdx.y];
    const size_t base = ((size_t)blockIdx.x * 256 + threadIdx.x) * 8;
    float4 f0 = *reinterpret_cast<const float4*>(src + base);
    float4 f1 = *reinterpret_cast<const float4*>(src + base + 4);
    __half2 h[4];
    h[0] = __floats2half2_rn(f0.x, f0.y);
    h[1] = __floats2half2_rn(f0.z, f0.w);
    h[2] = __floats2half2_rn(f1.x, f1.y);
    h[3] = __floats2half2_rn(f1.z, f1.w);
    *reinterpret_cast<uint4*>(dst + base) = *reinterpret_cast<uint4*>(h);
}

// ---- prep: weights transposed to [n][k] fp16 ----
__global__ void wprep_kernel(const float* __restrict__ w1, const float* __restrict__ w2,
                             const float* __restrict__ a1, const float* __restrict__ a2) {
    const int z = blockIdx.x;
    const float* src = (z == 0) ? a1 : (z == 1) ? a2 : (z == 2) ? w1 : w2;
    const int n = threadIdx.x;
    const int k0 = blockIdx.y * 32;
    for (int k = k0; k < k0 + 32; ++k)
        g_W[z][n * DIM + k] = __float2half_rn(src[k * DIM + n]);
}

extern "C" void kernel_launch(void* const* d_in, const int* in_sizes, int n_in,
                              void* d_out, int out_size) {
    const float* i0 = (const float*)d_in[0];
    const float* i1 = (const float*)d_in[1];
    const float* W1 = (const float*)d_in[2];
    const float* W2 = (const float*)d_in[3];
    const float* A1 = (const float*)d_in[4];
    const float* A2 = (const float*)d_in[5];
    float* out = (float*)d_out;

    const int rows = in_sizes[0] / DIM;           // 65536
    xprep_kernel<<<dim3((unsigned)(in_sizes[0] / (256 * 8)), 2), 256>>>(i0, i1);
    wprep_kernel<<<dim3(4, 8), 256>>>(W1, W2, A1, A2);

    cudaFuncSetAttribute(fused_mma_kernel,
                         cudaFuncAttributeMaxDynamicSharedMemorySize, SMEM_BYTES);
    fused_mma_kernel<<<rows / TM, THREADS, SMEM_BYTES>>>(i0, i1, out);
    (void)n_in; (void)out_size;
}

// round 12
// speedup vs baseline: 7.9989x; 1.0002x over previous
#include <cuda_runtime.h>
#include <cuda_fp16.h>
#include <cstdint>
#include <math.h>

#define DIM 256
#define TM 64
#define THREADS 256
#define NJOBS 16                  // 4 passes x 4 chunks (KC=64)

#define PXB 144                   // smem row stride BYTES (72 fp16): conflict-free ldsm
#define XS_BYTES (TM * PXB)       // 9216
#define WS_BYTES (256 * PXB)      // 36864
#define BUF_BYTES (XS_BYTES + WS_BYTES)   // 46080
#define SMEM_BYTES (2 * BUF_BYTES)        // 92160 -> 2 CTAs/SM

#define NROWS 16777216            // 4*32*512*256

__device__ __half g_X[2][NROWS];        // fp16 copies of i0, i1
__device__ __half g_W[4][DIM * DIM];    // [n][k] transposed fp16

__device__ __forceinline__ uint32_t smem_u32(const void* p) {
    uint32_t a;
    asm("{ .reg .u64 t; cvta.to.shared.u64 t, %1; cvt.u32.u64 %0, t; }" : "=r"(a) : "l"(p));
    return a;
}
__device__ __forceinline__ void cp16(uint32_t s, const void* g) {
    asm volatile("cp.async.cg.shared.global [%0], [%1], 16;" :: "r"(s), "l"(g));
}
#define CP_COMMIT() asm volatile("cp.async.commit_group;" ::: "memory")
#define CP_WAIT(n)  asm volatile("cp.async.wait_group %0;" :: "n"(n) : "memory")

__device__ __forceinline__ void ldsm4(uint32_t* r, uint32_t addr) {
    asm volatile("ldmatrix.sync.aligned.m8n8.x4.shared.b16 {%0,%1,%2,%3}, [%4];"
                 : "=r"(r[0]), "=r"(r[1]), "=r"(r[2]), "=r"(r[3]) : "r"(addr));
}
__device__ __forceinline__ void mma16(float* c, const uint32_t* a, const uint32_t* b) {
    asm volatile(
        "mma.sync.aligned.m16n8k16.row.col.f32.f16.f16.f32 "
        "{%0,%1,%2,%3}, {%4,%5,%6,%7}, {%8,%9}, {%0,%1,%2,%3};"
        : "+f"(c[0]), "+f"(c[1]), "+f"(c[2]), "+f"(c[3])
        : "r"(a[0]), "r"(a[1]), "r"(a[2]), "r"(a[3]), "r"(b[0]), "r"(b[1]));
}

// ---- one KC=64 chunk: acc(32x64 warptile) += X @ W, software-pipelined ----
// All buffer indices are compile-time constants under full unroll.
__device__ __forceinline__ void gemm_chunk(uint32_t a_base, uint32_t b_base,
                                           float (&acc)[2][8][4]) {
    uint32_t ua[2][2][4];                          // A double buffer across ks
    ldsm4(ua[0][0], a_base);
    ldsm4(ua[0][1], a_base + 16 * PXB);
#pragma unroll
    for (int ks = 0; ks < 4; ++ks) {               // k16 steps
        const int cur = ks & 1, nxt = cur ^ 1;     // static under unroll
        uint32_t b[4][4];
        ldsm4(b[0], b_base + 0 * (16 * PXB) + ks * 32);
        ldsm4(b[1], b_base + 1 * (16 * PXB) + ks * 32);
        ldsm4(b[2], b_base + 2 * (16 * PXB) + ks * 32);
        ldsm4(b[3], b_base + 3 * (16 * PXB) + ks * 32);
        if (ks < 3) {                              // prefetch A for ks+1
            ldsm4(ua[nxt][0], a_base + (ks + 1) * 32);
            ldsm4(ua[nxt][1], a_base + 16 * PXB + (ks + 1) * 32);
        }
#pragma unroll
        for (int nt2 = 0; nt2 < 4; ++nt2) {
            mma16(acc[0][2 * nt2],     ua[cur][0], b[nt2]);
            mma16(acc[1][2 * nt2],     ua[cur][1], b[nt2]);
            mma16(acc[0][2 * nt2 + 1], ua[cur][0], b[nt2] + 2);
            mma16(acc[1][2 * nt2 + 1], ua[cur][1], b[nt2] + 2);
        }
    }
}

__device__ __forceinline__ void zero_acc(float (&acc)[2][8][4]) {
#pragma unroll
    for (int mt = 0; mt < 2; ++mt)
#pragma unroll
        for (int nt = 0; nt < 8; ++nt)
#pragma unroll
            for (int q = 0; q < 4; ++q) acc[mt][nt][q] = 0.f;
}

// rowdot(acc, Xo_fp16) -> partial sums in s_g
__device__ __forceinline__ void gate_dot(const __half* __restrict__ Xo,
                                         const float (&acc)[2][8][4], int g,
                                         int wm, int wn, int lq, int lr,
                                         float (*s_g)[4][TM]) {
    float pr[2][2] = {{0.f, 0.f}, {0.f, 0.f}};
#pragma unroll
    for (int mt = 0; mt < 2; ++mt) {
        const int r0 = wm * 32 + mt * 16 + lq;
#pragma unroll
        for (int nt = 0; nt < 8; ++nt) {
            const int cb = wn * 64 + nt * 8 + lr * 2;
            float2 v0 = __half22float2(*reinterpret_cast<const __half2*>(Xo + (size_t)r0 * DIM + cb));
            float2 v1 = __half22float2(*reinterpret_cast<const __half2*>(Xo + (size_t)(r0 + 8) * DIM + cb));
            pr[mt][0] += acc[mt][nt][0] * v0.x + acc[mt][nt][1] * v0.y;
            pr[mt][1] += acc[mt][nt][2] * v1.x + acc[mt][nt][3] * v1.y;
        }
    }
#pragma unroll
    for (int off = 1; off <= 2; off <<= 1)
#pragma unroll
        for (int mt = 0; mt < 2; ++mt) {
            pr[mt][0] += __shfl_xor_sync(0xFFFFFFFFu, pr[mt][0], off);
            pr[mt][1] += __shfl_xor_sync(0xFFFFFFFFu, pr[mt][1], off);
        }
    if (lr == 0) {
#pragma unroll
        for (int mt = 0; mt < 2; ++mt) {
            s_g[g][wn][wm * 32 + mt * 16 + lq] = pr[mt][0];
            s_g[g][wn][wm * 32 + mt * 16 + lq + 8] = pr[mt][1];
        }
    }
}

__global__ void __launch_bounds__(THREADS, 2)
fused_mma_kernel(float* __restrict__ out) {
    extern __shared__ char dyn[];
    __shared__ float s_g[2][4][TM];
    __shared__ float s_sc[2][TM];

    const int tid = threadIdx.x;
    const int l = tid & 31, w = tid >> 5;
    const int wm = w >> 2, wn = w & 3;            // m-split 2, n-split 4
    const int lq = l >> 2, lr = l & 3;
    const size_t rowbase = (size_t)blockIdx.x * TM;
    const __half* X0h = g_X[0] + rowbase * DIM;
    const __half* X1h = g_X[1] + rowbase * DIM;
    const uint32_t sb = smem_u32(dyn);

    // per-lane ldsm addressing (canonical fp16 recipes)
    const uint32_t a_off = (uint32_t)(wm * 32 + (l & 7) + ((l >> 3) & 1) * 8) * PXB
                         + (uint32_t)((l >> 4) & 1) * 16;
    const uint32_t b_off = XS_BYTES
                         + (uint32_t)(wn * 64 + ((l >> 4) & 1) * 8 + (l & 7)) * PXB
                         + (uint32_t)((l >> 3) & 1) * 16;

    // jobs 0..15: pass p=j>>2, chunk c=j&3 (KC=64)
    //  p0: A=X1h,B=attn1 -> g0 dot X0   p1: A=X0h,B=attn2 -> g1 dot X1
    //  p2: A=X0h,B=W1 (raw)             p3: A=X1h,B=W2 (raw; acc rescaled)
    auto stage = [&](int j) {
        const int p = j >> 2, c = j & 3;
        const __half* As = (p == 0 || p == 3) ? X1h : X0h;
        const __half* Bs = g_W[p];
        const uint32_t base = sb + (uint32_t)(j & 1) * BUF_BYTES;
#pragma unroll
        for (int t = 0; t < 2; ++t) {             // X chunk: 64 rows x 64 fp16
            const int id = tid + t * THREADS;
            const int r = id >> 3, gk = id & 7;
            cp16(base + (uint32_t)(r * PXB + gk * 16), As + r * DIM + c * 64 + gk * 8);
        }
#pragma unroll
        for (int t = 0; t < 8; ++t) {             // W chunk: 256 n x 64 k fp16
            const int id = tid + t * THREADS;
            const int n = id >> 3, gk = id & 7;
            cp16(base + (uint32_t)(XS_BYTES + n * PXB + gk * 16),
                 Bs + n * DIM + c * 64 + gk * 8);
        }
        CP_COMMIT();
    };

    float acc[2][8][4];
    zero_acc(acc);

    stage(0);
    stage(1);

    for (int j = 0; j < NJOBS; ++j) {
        if (j == NJOBS - 1) { CP_WAIT(0); } else { CP_WAIT(1); }
        __syncthreads();
        const uint32_t base = sb + (uint32_t)(j & 1) * BUF_BYTES;
        gemm_chunk(base + a_off, base + b_off, acc);

        if (j == 3) {                             // g0 = rowdot(U0, X0)
            gate_dot(X0h, acc, 0, wm, wn, lq, lr, s_g);
            zero_acc(acc);
        }
        if (j == 7) {                             // g1; sigmoid -> s0, s1
            gate_dot(X1h, acc, 1, wm, wn, lq, lr, s_g);
            __syncthreads();
            if (tid < TM) {
                const float g0 = s_g[0][0][tid] + s_g[0][1][tid] + s_g[0][2][tid] + s_g[0][3][tid];
                const float g1 = s_g[1][0][tid] + s_g[1][1][tid] + s_g[1][2][tid] + s_g[1][3][tid];
                s_sc[0][tid] = 1.f + 1.f / (1.f + expf(-g0));
                s_sc[1][tid] = 1.f + 1.f / (1.f + expf(-g1));
            }
            __syncthreads();
            zero_acc(acc);
        }
        if (j == 11) {                            // acc = P0 -> scale by s0/s1 (fp32 exact)
#pragma unroll
            for (int mt = 0; mt < 2; ++mt) {
                const int r0 = wm * 32 + mt * 16 + lq;
                const float rt0 = s_sc[0][r0] / s_sc[1][r0];
                const float rt1 = s_sc[0][r0 + 8] / s_sc[1][r0 + 8];
#pragma unroll
                for (int nt = 0; nt < 8; ++nt) {
                    acc[mt][nt][0] *= rt0; acc[mt][nt][1] *= rt0;
                    acc[mt][nt][2] *= rt1; acc[mt][nt][3] *= rt1;
                }
            }
        }
        __syncthreads();                          // all reads of buf j done
        if (j + 2 < NJOBS) stage(j + 2);
    }

    // epilogue: out = s1 * acc = s0*P0 + s1*P1
#pragma unroll
    for (int mt = 0; mt < 2; ++mt) {
        const int r0 = wm * 32 + mt * 16 + lq;
        const float f0 = s_sc[1][r0];
        const float f1 = s_sc[1][r0 + 8];
#pragma unroll
        for (int nt = 0; nt < 8; ++nt) {
            const int cb = wn * 64 + nt * 8 + lr * 2;
            float2 v0 = make_float2(acc[mt][nt][0] * f0, acc[mt][nt][1] * f0);
            float2 v1 = make_float2(acc[mt][nt][2] * f1, acc[mt][nt][3] * f1);
            *reinterpret_cast<float2*>(out + (rowbase + r0) * DIM + cb) = v0;
            *reinterpret_cast<float2*>(out + (rowbase + r0 + 8) * DIM + cb) = v1;
        }
    }
}

// ---- prep: inputs fp32 -> fp16 ----
__global__ void xprep_kernel(const float* __restrict__ i0, const float* __restrict__ i1) {
    const float* src = blockIdx.y ? i1 : i0;
    __half* dst = g_X[blockIdx.y];
    const size_t base = ((size_t)blockIdx.x * 256 + threadIdx.x) * 8;
    float4 f0 = *reinterpret_cast<const float4*>(src + base);
    float4 f1 = *reinterpret_cast<const float4*>(src + base + 4);
    __half2 h[4];
    h[0] = __floats2half2_rn(f0.x, f0.y);
    h[1] = __floats2half2_rn(f0.z, f0.w);
    h[2] = __floats2half2_rn(f1.x, f1.y);
    h[3] = __floats2half2_rn(f1.z, f1.w);
    *reinterpret_cast<uint4*>(dst + base) = *reinterpret_cast<uint4*>(h);
}

// ---- prep: weights transposed to [n][k] fp16 ----
__global__ void wprep_kernel(const float* __restrict__ w1, const float* __restrict__ w2,
                             const float* __restrict__ a1, const float* __restrict__ a2) {
    const int z = blockIdx.x;
    const float* src = (z == 0) ? a1 : (z == 1) ? a2 : (z == 2) ? w1 : w2;
    const int n = threadIdx.x;
    const int k0 = blockIdx.y * 32;
    for (int k = k0; k < k0 + 32; ++k)
        g_W[z][n * DIM + k] = __float2half_rn(src[k * DIM + n]);
}

extern "C" void kernel_launch(void* const* d_in, const int* in_sizes, int n_in,
                              void* d_out, int out_size) {
    const float* i0 = (const float*)d_in[0];
    const float* i1 = (const float*)d_in[1];
    const float* W1 = (const float*)d_in[2];
    const float* W2 = (const float*)d_in[3];
    const float* A1 = (const float*)d_in[4];
    const float* A2 = (const float*)d_in[5];
    float* out = (float*)d_out;

    const int rows = in_sizes[0] / DIM;           // 65536
    xprep_kernel<<<dim3((unsigned)(in_sizes[0] / (256 * 8)), 2), 256>>>(i0, i1);
    wprep_kernel<<<dim3(4, 8), 256>>>(W1, W2, A1, A2);

    cudaFuncSetAttribute(fused_mma_kernel,
                         cudaFuncAttributeMaxDynamicSharedMemorySize, SMEM_BYTES);
    fused_mma_kernel<<<rows / TM, THREADS, SMEM_BYTES>>>(out);
    (void)n_in; (void)out_size;
}

// round 13
// speedup vs baseline: 8.4042x; 1.0507x over previous
#include <cuda_runtime.h>
#include <cuda_fp16.h>
#include <cstdint>
#include <math.h>

#define DIM 256
#define TM 64
#define THREADS 256
#define NJOBS 32                  // 4 passes x 8 chunks (KC=32)

#define XH_STR 528                // fp16 X row stride bytes (256 halfs + 16B pad)
#define XH_SZ  (TM * XH_STR)      // 33792 per input
#define WOFF   (2 * XH_SZ)        // 67584
#define WROW   80                 // weight smem row stride bytes (32 halfs + 16B pad)
#define WBUF   (256 * WROW)       // 20480
#define STG_STR 1056              // fp32 staging row stride bytes (256 floats + 32B pad)
#define STG_SZ  (16 * STG_STR)    // 16896
#define SMEM_BYTES (WOFF + 2 * WBUF)   // 108544 -> 2 CTAs/SM

__device__ __half g_W[4][DIM * DIM];   // [n][k] transposed fp16: attn1, attn2, W1, W2

__device__ __forceinline__ uint32_t smem_u32(const void* p) {
    uint32_t a;
    asm("{ .reg .u64 t; cvta.to.shared.u64 t, %1; cvt.u32.u64 %0, t; }" : "=r"(a) : "l"(p));
    return a;
}
__device__ __forceinline__ void cp16(uint32_t s, const void* g) {
    asm volatile("cp.async.cg.shared.global [%0], [%1], 16;" :: "r"(s), "l"(g));
}
#define CP_COMMIT() asm volatile("cp.async.commit_group;" ::: "memory")
#define CP_WAIT(n)  asm volatile("cp.async.wait_group %0;" :: "n"(n) : "memory")

__device__ __forceinline__ void ldsm4(uint32_t* r, uint32_t addr) {
    asm volatile("ldmatrix.sync.aligned.m8n8.x4.shared.b16 {%0,%1,%2,%3}, [%4];"
                 : "=r"(r[0]), "=r"(r[1]), "=r"(r[2]), "=r"(r[3]) : "r"(addr));
}
__device__ __forceinline__ void mma16(float* c, const uint32_t* a, const uint32_t* b) {
    asm volatile(
        "mma.sync.aligned.m16n8k16.row.col.f32.f16.f16.f32 "
        "{%0,%1,%2,%3}, {%4,%5,%6,%7}, {%8,%9}, {%0,%1,%2,%3};"
        : "+f"(c[0]), "+f"(c[1]), "+f"(c[2]), "+f"(c[3])
        : "r"(a[0]), "r"(a[1]), "r"(a[2]), "r"(a[3]), "r"(b[0]), "r"(b[1]));
}

// ---- one KC=32 chunk: acc(32x64 warptile) += X @ W ----
__device__ __forceinline__ void gemm_chunk(uint32_t a_base, uint32_t b_base,
                                           float (&acc)[2][8][4]) {
#pragma unroll
    for (int ks = 0; ks < 2; ++ks) {              // k16 steps
        uint32_t ua[2][4];
        ldsm4(ua[0], a_base + ks * 32);
        ldsm4(ua[1], a_base + 16 * XH_STR + ks * 32);
#pragma unroll
        for (int nt2 = 0; nt2 < 4; ++nt2) {
            uint32_t b[4];
            ldsm4(b, b_base + nt2 * (16 * WROW) + ks * 32);
            mma16(acc[0][2 * nt2],     ua[0], b);
            mma16(acc[1][2 * nt2],     ua[1], b);
            mma16(acc[0][2 * nt2 + 1], ua[0], b + 2);
            mma16(acc[1][2 * nt2 + 1], ua[1], b + 2);
        }
    }
}

__device__ __forceinline__ void zero_acc(float (&acc)[2][8][4]) {
#pragma unroll
    for (int mt = 0; mt < 2; ++mt)
#pragma unroll
        for (int nt = 0; nt < 8; ++nt)
#pragma unroll
            for (int q = 0; q < 4; ++q) acc[mt][nt][q] = 0.f;
}

// rowdot(acc, X_smem_fp16) -> partial sums in s_g; conflict-free (bank=4lq+lr)
__device__ __forceinline__ void gate_dot(const char* __restrict__ Xs,
                                         const float (&acc)[2][8][4], int g,
                                         int wm, int wn, int lq, int lr,
                                         float (*s_g)[4][TM]) {
    float pr[2][2] = {{0.f, 0.f}, {0.f, 0.f}};
#pragma unroll
    for (int mt = 0; mt < 2; ++mt) {
        const int r0 = wm * 32 + mt * 16 + lq;
#pragma unroll
        for (int nt = 0; nt < 8; ++nt) {
            const int cb = (wn * 64 + nt * 8 + lr * 2) * 2;   // bytes
            float2 v0 = __half22float2(*reinterpret_cast<const __half2*>(Xs + r0 * XH_STR + cb));
            float2 v1 = __half22float2(*reinterpret_cast<const __half2*>(Xs + (r0 + 8) * XH_STR + cb));
            pr[mt][0] += acc[mt][nt][0] * v0.x + acc[mt][nt][1] * v0.y;
            pr[mt][1] += acc[mt][nt][2] * v1.x + acc[mt][nt][3] * v1.y;
        }
    }
#pragma unroll
    for (int off = 1; off <= 2; off <<= 1)
#pragma unroll
        for (int mt = 0; mt < 2; ++mt) {
            pr[mt][0] += __shfl_xor_sync(0xFFFFFFFFu, pr[mt][0], off);
            pr[mt][1] += __shfl_xor_sync(0xFFFFFFFFu, pr[mt][1], off);
        }
    if (lr == 0) {
#pragma unroll
        for (int mt = 0; mt < 2; ++mt) {
            s_g[g][wn][wm * 32 + mt * 16 + lq] = pr[mt][0];
            s_g[g][wn][wm * 32 + mt * 16 + lq + 8] = pr[mt][1];
        }
    }
}

__global__ void __launch_bounds__(THREADS, 2)
fused_mma_kernel(const float* __restrict__ i0, const float* __restrict__ i1,
                 float* __restrict__ out) {
    extern __shared__ char dyn[];
    __shared__ float s_g[2][4][TM];
    __shared__ float s_sc[2][TM];

    const int tid = threadIdx.x;
    const int l = tid & 31, w = tid >> 5;
    const int wm = w >> 2, wn = w & 3;            // m-split 2, n-split 4
    const int lq = l >> 2, lr = l & 3;
    const size_t rowbase = (size_t)blockIdx.x * TM;
    const uint32_t sb = smem_u32(dyn);

    // ---------- prologue: X fp32 -> persistent fp16 smem region ----------
    // 8 chunks: input s>>2, rows (s&3)*16 .. +15, staged through W-buffer space.
    auto xstage = [&](int s) {
        const float* src = ((s >> 2) ? i1 : i0) + rowbase * DIM + (size_t)(s & 3) * 16 * DIM;
        const uint32_t stg = sb + WOFF + (uint32_t)(s & 1) * STG_SZ;
#pragma unroll
        for (int t = 0; t < 4; ++t) {
            const int id = tid + t * THREADS;
            const int r = id >> 6, c4 = id & 63;
            cp16(stg + (uint32_t)(r * STG_STR + c4 * 16), src + r * DIM + c4 * 4);
        }
        CP_COMMIT();
    };
    auto xconv = [&](int s) {
        const int r = tid >> 4, cg = tid & 15;
        const char* sp = dyn + WOFF + (s & 1) * STG_SZ + r * STG_STR + cg * 64;
        float4 f0 = *reinterpret_cast<const float4*>(sp);
        float4 f1 = *reinterpret_cast<const float4*>(sp + 16);
        float4 f2 = *reinterpret_cast<const float4*>(sp + 32);
        float4 f3 = *reinterpret_cast<const float4*>(sp + 48);
        __half2 h[8];
        h[0] = __floats2half2_rn(f0.x, f0.y); h[1] = __floats2half2_rn(f0.z, f0.w);
        h[2] = __floats2half2_rn(f1.x, f1.y); h[3] = __floats2half2_rn(f1.z, f1.w);
        h[4] = __floats2half2_rn(f2.x, f2.y); h[5] = __floats2half2_rn(f2.z, f2.w);
        h[6] = __floats2half2_rn(f3.x, f3.y); h[7] = __floats2half2_rn(f3.z, f3.w);
        char* dp = dyn + (s >> 2) * XH_SZ + ((s & 3) * 16 + r) * XH_STR + cg * 32;
        *reinterpret_cast<uint4*>(dp)      = *reinterpret_cast<const uint4*>(h);
        *reinterpret_cast<uint4*>(dp + 16) = *reinterpret_cast<const uint4*>(h + 4);
    };

    xstage(0); xstage(1);
    for (int s = 0; s < 8; ++s) {
        if (s < 7) { CP_WAIT(1); } else { CP_WAIT(0); }
        __syncthreads();
        xconv(s);
        __syncthreads();
        if (s + 2 < 8) xstage(s + 2);
    }
    CP_WAIT(0);
    __syncthreads();

    // ---------- per-lane ldsm addressing ----------
    const uint32_t a_off = (uint32_t)((wm * 32 + (l & 7) + ((l >> 3) & 1) * 8) * XH_STR)
                         + (uint32_t)((l >> 4) & 1) * 16;
    const uint32_t b_off = (uint32_t)((wn * 64 + ((l >> 4) & 1) * 8 + (l & 7)) * WROW)
                         + (uint32_t)((l >> 3) & 1) * 16;

    // jobs 0..31: pass p=j>>3, chunk c=j&7 (KC=32). Weights only.
    //  p0: A=X1h,B=attn1 -> g0 dot X0   p1: A=X0h,B=attn2 -> g1 dot X1
    //  p2: A=X0h,B=W1 (raw)             p3: A=X1h,B=W2 (raw; acc rescaled)
    auto stage = [&](int j) {
        const int p = j >> 3, c = j & 7;
        const __half* Bs = g_W[p];
        const uint32_t base = sb + WOFF + (uint32_t)(j & 1) * WBUF;
#pragma unroll
        for (int t = 0; t < 4; ++t) {             // 256 n x 32 k fp16 = 16KB
            const int id = tid + t * THREADS;
            const int n = id >> 2, gk = id & 3;
            cp16(base + (uint32_t)(n * WROW + gk * 16), Bs + n * DIM + c * 32 + gk * 8);
        }
        CP_COMMIT();
    };

    float acc[2][8][4];
    zero_acc(acc);

    stage(0);
    stage(1);

    for (int j = 0; j < NJOBS; ++j) {
        if (j == NJOBS - 1) { CP_WAIT(0); } else { CP_WAIT(1); }
        __syncthreads();
        const int p = j >> 3, c = j & 7;
        const int ainp = (p == 0 || p == 3) ? 1 : 0;
        const uint32_t a_base = sb + (uint32_t)ainp * XH_SZ + a_off + (uint32_t)c * 64;
        const uint32_t b_base = sb + WOFF + (uint32_t)(j & 1) * WBUF + b_off;
        gemm_chunk(a_base, b_base, acc);

        if (j == 7) {                             // g0 = rowdot(U0, X0)
            gate_dot(dyn, acc, 0, wm, wn, lq, lr, s_g);
            zero_acc(acc);
        }
        if (j == 15) {                            // g1; sigmoid -> s0, s1
            gate_dot(dyn + XH_SZ, acc, 1, wm, wn, lq, lr, s_g);
            __syncthreads();
            if (tid < TM) {
                const float g0 = s_g[0][0][tid] + s_g[0][1][tid] + s_g[0][2][tid] + s_g[0][3][tid];
                const float g1 = s_g[1][0][tid] + s_g[1][1][tid] + s_g[1][2][tid] + s_g[1][3][tid];
                s_sc[0][tid] = 1.f + 1.f / (1.f + expf(-g0));
                s_sc[1][tid] = 1.f + 1.f / (1.f + expf(-g1));
            }
            __syncthreads();
            zero_acc(acc);
        }
        if (j == 23) {                            // acc = P0 -> scale by s0/s1 (fp32 exact)
#pragma unroll
            for (int mt = 0; mt < 2; ++mt) {
                const int r0 = wm * 32 + mt * 16 + lq;
                const float rt0 = s_sc[0][r0] / s_sc[1][r0];
                const float rt1 = s_sc[0][r0 + 8] / s_sc[1][r0 + 8];
#pragma unroll
                for (int nt = 0; nt < 8; ++nt) {
                    acc[mt][nt][0] *= rt0; acc[mt][nt][1] *= rt0;
                    acc[mt][nt][2] *= rt1; acc[mt][nt][3] *= rt1;
                }
            }
        }
        __syncthreads();                          // all reads of buf j done
        if (j + 2 < NJOBS) stage(j + 2);
    }

    // epilogue: out = s1 * acc = s0*P0 + s1*P1
#pragma unroll
    for (int mt = 0; mt < 2; ++mt) {
        const int r0 = wm * 32 + mt * 16 + lq;
        const float f0 = s_sc[1][r0];
        const float f1 = s_sc[1][r0 + 8];
#pragma unroll
        for (int nt = 0; nt < 8; ++nt) {
            const int cb = wn * 64 + nt * 8 + lr * 2;
            float2 v0 = make_float2(acc[mt][nt][0] * f0, acc[mt][nt][1] * f0);
            float2 v1 = make_float2(acc[mt][nt][2] * f1, acc[mt][nt][3] * f1);
            *reinterpret_cast<float2*>(out + (rowbase + r0) * DIM + cb) = v0;
            *reinterpret_cast<float2*>(out + (rowbase + r0 + 8) * DIM + cb) = v1;
        }
    }
}

// ---- prep: weights transposed to [n][k] fp16 ----
__global__ void wprep_kernel(const float* __restrict__ w1, const float* __restrict__ w2,
                             const float* __restrict__ a1, const float* __restrict__ a2) {
    const int z = blockIdx.x;
    const float* src = (z == 0) ? a1 : (z == 1) ? a2 : (z == 2) ? w1 : w2;
    const int n = threadIdx.x;
    const int k0 = blockIdx.y * 32;
    for (int k = k0; k < k0 + 32; ++k)
        g_W[z][n * DIM + k] = __float2half_rn(src[k * DIM + n]);
}

extern "C" void kernel_launch(void* const* d_in, const int* in_sizes, int n_in,
                              void* d_out, int out_size) {
    const float* i0 = (const float*)d_in[0];
    const float* i1 = (const float*)d_in[1];
    const float* W1 = (const float*)d_in[2];
    const float* W2 = (const float*)d_in[3];
    const float* A1 = (const float*)d_in[4];
    const float* A2 = (const float*)d_in[5];
    float* out = (float*)d_out;

    wprep_kernel<<<dim3(4, 8), 256>>>(W1, W2, A1, A2);

    cudaFuncSetAttribute(fused_mma_kernel,
                         cudaFuncAttributeMaxDynamicSharedMemorySize, SMEM_BYTES);
    const int rows = in_sizes[0] / DIM;           // 65536
    fused_mma_kernel<<<rows / TM, THREADS, SMEM_BYTES>>>(i0, i1, out);
    (void)n_in; (void)out_size;
}

// round 14
// speedup vs baseline: 8.4536x; 1.0059x over previous
#include <cuda_runtime.h>
#include <cuda_fp16.h>
#include <cstdint>
#include <math.h>

#define DIM 256
#define TM 64
#define THREADS 256
#define NJOBS 32                  // 4 passes x 8 chunks (KC=32)

#define XH_STR 528                // fp16 X row stride bytes (256 halfs + 16B pad)
#define XH_SZ  (TM * XH_STR)      // 33792 per input
#define WOFF   (2 * XH_SZ)        // 67584
#define WROW   80                 // weight smem row stride bytes (32 halfs + 16B pad)
#define WBUF   (256 * WROW)       // 20480
#define SMEM_BYTES (WOFF + 2 * WBUF)   // 108544 -> 2 CTAs/SM

__device__ __half g_W[4][DIM * DIM];   // [n][k] transposed fp16: attn1, attn2, W1, W2

__device__ __forceinline__ uint32_t smem_u32(const void* p) {
    uint32_t a;
    asm("{ .reg .u64 t; cvta.to.shared.u64 t, %1; cvt.u32.u64 %0, t; }" : "=r"(a) : "l"(p));
    return a;
}
__device__ __forceinline__ void cp16(uint32_t s, const void* g) {
    asm volatile("cp.async.cg.shared.global [%0], [%1], 16;" :: "r"(s), "l"(g));
}
#define CP_COMMIT() asm volatile("cp.async.commit_group;" ::: "memory")
#define CP_WAIT(n)  asm volatile("cp.async.wait_group %0;" :: "n"(n) : "memory")

__device__ __forceinline__ void ldsm4(uint32_t* r, uint32_t addr) {
    asm volatile("ldmatrix.sync.aligned.m8n8.x4.shared.b16 {%0,%1,%2,%3}, [%4];"
                 : "=r"(r[0]), "=r"(r[1]), "=r"(r[2]), "=r"(r[3]) : "r"(addr));
}
__device__ __forceinline__ void mma16(float* c, const uint32_t* a, const uint32_t* b) {
    asm volatile(
        "mma.sync.aligned.m16n8k16.row.col.f32.f16.f16.f32 "
        "{%0,%1,%2,%3}, {%4,%5,%6,%7}, {%8,%9}, {%0,%1,%2,%3};"
        : "+f"(c[0]), "+f"(c[1]), "+f"(c[2]), "+f"(c[3])
        : "r"(a[0]), "r"(a[1]), "r"(a[2]), "r"(a[3]), "r"(b[0]), "r"(b[1]));
}

// ---- one KC=32 chunk: acc(32x64 warptile) += X @ W ----
__device__ __forceinline__ void gemm_chunk(uint32_t a_base, uint32_t b_base,
                                           float (&acc)[2][8][4]) {
#pragma unroll
    for (int ks = 0; ks < 2; ++ks) {              // k16 steps
        uint32_t ua[2][4];
        ldsm4(ua[0], a_base + ks * 32);
        ldsm4(ua[1], a_base + 16 * XH_STR + ks * 32);
#pragma unroll
        for (int nt2 = 0; nt2 < 4; ++nt2) {
            uint32_t b[4];
            ldsm4(b, b_base + nt2 * (16 * WROW) + ks * 32);
            mma16(acc[0][2 * nt2],     ua[0], b);
            mma16(acc[1][2 * nt2],     ua[1], b);
            mma16(acc[0][2 * nt2 + 1], ua[0], b + 2);
            mma16(acc[1][2 * nt2 + 1], ua[1], b + 2);
        }
    }
}

__device__ __forceinline__ void zero_acc(float (&acc)[2][8][4]) {
#pragma unroll
    for (int mt = 0; mt < 2; ++mt)
#pragma unroll
        for (int nt = 0; nt < 8; ++nt)
#pragma unroll
            for (int q = 0; q < 4; ++q) acc[mt][nt][q] = 0.f;
}

// rowdot(acc, X_smem_fp16) -> partial sums in s_g; conflict-free (bank=4lq+lr)
__device__ __forceinline__ void gate_dot(const char* __restrict__ Xs,
                                         const float (&acc)[2][8][4], int g,
                                         int wm, int wn, int lq, int lr,
                                         float (*s_g)[4][TM]) {
    float pr[2][2] = {{0.f, 0.f}, {0.f, 0.f}};
#pragma unroll
    for (int mt = 0; mt < 2; ++mt) {
        const int r0 = wm * 32 + mt * 16 + lq;
#pragma unroll
        for (int nt = 0; nt < 8; ++nt) {
            const int cb = (wn * 64 + nt * 8 + lr * 2) * 2;   // bytes
            float2 v0 = __half22float2(*reinterpret_cast<const __half2*>(Xs + r0 * XH_STR + cb));
            float2 v1 = __half22float2(*reinterpret_cast<const __half2*>(Xs + (r0 + 8) * XH_STR + cb));
            pr[mt][0] += acc[mt][nt][0] * v0.x + acc[mt][nt][1] * v0.y;
            pr[mt][1] += acc[mt][nt][2] * v1.x + acc[mt][nt][3] * v1.y;
        }
    }
#pragma unroll
    for (int off = 1; off <= 2; off <<= 1)
#pragma unroll
        for (int mt = 0; mt < 2; ++mt) {
            pr[mt][0] += __shfl_xor_sync(0xFFFFFFFFu, pr[mt][0], off);
            pr[mt][1] += __shfl_xor_sync(0xFFFFFFFFu, pr[mt][1], off);
        }
    if (lr == 0) {
#pragma unroll
        for (int mt = 0; mt < 2; ++mt) {
            s_g[g][wn][wm * 32 + mt * 16 + lq] = pr[mt][0];
            s_g[g][wn][wm * 32 + mt * 16 + lq + 8] = pr[mt][1];
        }
    }
}

__global__ void __launch_bounds__(THREADS, 2)
fused_mma_kernel(const float* __restrict__ i0, const float* __restrict__ i1,
                 float* __restrict__ out) {
    extern __shared__ char dyn[];
    __shared__ float s_g[2][4][TM];
    __shared__ float s_sc[2][TM];

    const int tid = threadIdx.x;
    const int l = tid & 31, w = tid >> 5;
    const int wm = w >> 2, wn = w & 3;            // m-split 2, n-split 4
    const int lq = l >> 2, lr = l & 3;
    const size_t rowbase = (size_t)blockIdx.x * TM;
    const uint32_t sb = smem_u32(dyn);

    // ---------- weight staging (independent of X; issued FIRST) ----------
    // jobs 0..31: pass p=j>>3, chunk c=j&7 (KC=32)
    auto stage = [&](int j) {
        const int p = j >> 3, c = j & 7;
        const __half* Bs = g_W[p];
        const uint32_t base = sb + WOFF + (uint32_t)(j & 1) * WBUF;
#pragma unroll
        for (int t = 0; t < 4; ++t) {             // 256 n x 32 k fp16 = 16KB
            const int id = tid + t * THREADS;
            const int n = id >> 2, gk = id & 3;
            cp16(base + (uint32_t)(n * WROW + gk * 16), Bs + n * DIM + c * 32 + gk * 8);
        }
        CP_COMMIT();
    };

    stage(0);                                     // overlap with X prologue
    stage(1);

    // ---------- prologue: direct LDG fp32 -> cvt -> STS fp16 ----------
    // warp w handles rows {w, w+8, ..} of each input; fully coalesced rows.
#pragma unroll
    for (int s = 0; s < 2; ++s) {
        const float* src = (s ? i1 : i0) + rowbase * DIM;
        char* dst = dyn + s * XH_SZ;
#pragma unroll
        for (int t = 0; t < 8; ++t) {
            const int id = tid + t * THREADS;     // 2048 ids = 64 rows x 32 groups
            const int r = id >> 5, cg = id & 31;  // 8 floats per group
            float4 f0 = *reinterpret_cast<const float4*>(src + r * DIM + cg * 8);
            float4 f1 = *reinterpret_cast<const float4*>(src + r * DIM + cg * 8 + 4);
            __half2 h[4];
            h[0] = __floats2half2_rn(f0.x, f0.y);
            h[1] = __floats2half2_rn(f0.z, f0.w);
            h[2] = __floats2half2_rn(f1.x, f1.y);
            h[3] = __floats2half2_rn(f1.z, f1.w);
            *reinterpret_cast<uint4*>(dst + r * XH_STR + cg * 16) =
                *reinterpret_cast<const uint4*>(h);
        }
    }
    __syncthreads();                              // X fp16 region ready

    // ---------- per-lane ldsm addressing ----------
    const uint32_t a_off = (uint32_t)((wm * 32 + (l & 7) + ((l >> 3) & 1) * 8) * XH_STR)
                         + (uint32_t)((l >> 4) & 1) * 16;
    const uint32_t b_off = (uint32_t)((wn * 64 + ((l >> 4) & 1) * 8 + (l & 7)) * WROW)
                         + (uint32_t)((l >> 3) & 1) * 16;

    //  p0: A=X1h,B=attn1 -> g0 dot X0   p1: A=X0h,B=attn2 -> g1 dot X1
    //  p2: A=X0h,B=W1 (raw)             p3: A=X1h,B=W2 (raw; acc rescaled)
    float acc[2][8][4];
    zero_acc(acc);

    for (int j = 0; j < NJOBS; ++j) {
        if (j == NJOBS - 1) { CP_WAIT(0); } else { CP_WAIT(1); }
        __syncthreads();
        const int p = j >> 3, c = j & 7;
        const int ainp = (p == 0 || p == 3) ? 1 : 0;
        const uint32_t a_base = sb + (uint32_t)ainp * XH_SZ + a_off + (uint32_t)c * 64;
        const uint32_t b_base = sb + WOFF + (uint32_t)(j & 1) * WBUF + b_off;
        gemm_chunk(a_base, b_base, acc);

        if (j == 7) {                             // g0 = rowdot(U0, X0)
            gate_dot(dyn, acc, 0, wm, wn, lq, lr, s_g);
            zero_acc(acc);
        }
        if (j == 15) {                            // g1; sigmoid -> s0, s1
            gate_dot(dyn + XH_SZ, acc, 1, wm, wn, lq, lr, s_g);
            __syncthreads();
            if (tid < TM) {
                const float g0 = s_g[0][0][tid] + s_g[0][1][tid] + s_g[0][2][tid] + s_g[0][3][tid];
                const float g1 = s_g[1][0][tid] + s_g[1][1][tid] + s_g[1][2][tid] + s_g[1][3][tid];
                s_sc[0][tid] = 1.f + 1.f / (1.f + expf(-g0));
                s_sc[1][tid] = 1.f + 1.f / (1.f + expf(-g1));
            }
            __syncthreads();
            zero_acc(acc);
        }
        if (j == 23) {                            // acc = P0 -> scale by s0/s1 (fp32 exact)
#pragma unroll
            for (int mt = 0; mt < 2; ++mt) {
                const int r0 = wm * 32 + mt * 16 + lq;
                const float rt0 = s_sc[0][r0] / s_sc[1][r0];
                const float rt1 = s_sc[0][r0 + 8] / s_sc[1][r0 + 8];
#pragma unroll
                for (int nt = 0; nt < 8; ++nt) {
                    acc[mt][nt][0] *= rt0; acc[mt][nt][1] *= rt0;
                    acc[mt][nt][2] *= rt1; acc[mt][nt][3] *= rt1;
                }
            }
        }
        __syncthreads();                          // all reads of buf j done
        if (j + 2 < NJOBS) stage(j + 2);
    }

    // epilogue: out = s1 * acc = s0*P0 + s1*P1
#pragma unroll
    for (int mt = 0; mt < 2; ++mt) {
        const int r0 = wm * 32 + mt * 16 + lq;
        const float f0 = s_sc[1][r0];
        const float f1 = s_sc[1][r0 + 8];
#pragma unroll
        for (int nt = 0; nt < 8; ++nt) {
            const int cb = wn * 64 + nt * 8 + lr * 2;
            float2 v0 = make_float2(acc[mt][nt][0] * f0, acc[mt][nt][1] * f0);
            float2 v1 = make_float2(acc[mt][nt][2] * f1, acc[mt][nt][3] * f1);
            *reinterpret_cast<float2*>(out + (rowbase + r0) * DIM + cb) = v0;
            *reinterpret_cast<float2*>(out + (rowbase + r0 + 8) * DIM + cb) = v1;
        }
    }
}

// ---- prep: weights transposed to [n][k] fp16 ----
__global__ void wprep_kernel(const float* __restrict__ w1, const float* __restrict__ w2,
                             const float* __restrict__ a1, const float* __restrict__ a2) {
    const int z = blockIdx.x;
    const float* src = (z == 0) ? a1 : (z == 1) ? a2 : (z == 2) ? w1 : w2;
    const int n = threadIdx.x;
    const int k0 = blockIdx.y * 32;
    for (int k = k0; k < k0 + 32; ++k)
        g_W[z][n * DIM + k] = __float2half_rn(src[k * DIM + n]);
}

extern "C" void kernel_launch(void* const* d_in, const int* in_sizes, int n_in,
                              void* d_out, int out_size) {
    const float* i0 = (const float*)d_in[0];
    const float* i1 = (const float*)d_in[1];
    const float* W1 = (const float*)d_in[2];
    const float* W2 = (const float*)d_in[3];
    const float* A1 = (const float*)d_in[4];
    const float* A2 = (const float*)d_in[5];
    float* out = (float*)d_out;

    wprep_kernel<<<dim3(4, 8), 256>>>(W1, W2, A1, A2);

    cudaFuncSetAttribute(fused_mma_kernel,
                         cudaFuncAttributeMaxDynamicSharedMemorySize, SMEM_BYTES);
    const int rows = in_sizes[0] / DIM;           // 65536
    fused_mma_kernel<<<rows / TM, THREADS, SMEM_BYTES>>>(i0, i1, out);
    (void)n_in; (void)out_size;
}

// round 15
// speedup vs baseline: 9.5445x; 1.1290x over previous
#include <cuda_runtime.h>
#include <cuda_fp16.h>
#include <cstdint>
#include <math.h>

#define DIM 256
#define TM 64
#define THREADS 256
#define NJOBS 32                  // 4 passes x 8 chunks (KC=32)

#define XINP 32768                // per-input X region: 64 rows x 512 B (swizzled)
#define WOFF 65536                // = 2*XINP
#define WBUF 16384                // 256 n x 64 B (swizzled, no pad)
#define SMEM_BYTES (WOFF + 3 * WBUF)   // 114688 -> 2 CTAs/SM

__device__ __half g_W[4][DIM * DIM];   // [n][k] transposed fp16

__device__ __forceinline__ uint32_t smem_u32(const void* p) {
    uint32_t a;
    asm("{ .reg .u64 t; cvta.to.shared.u64 t, %1; cvt.u32.u64 %0, t; }" : "=r"(a) : "l"(p));
    return a;
}
__device__ __forceinline__ void cp16(uint32_t s, const void* g) {
    asm volatile("cp.async.cg.shared.global [%0], [%1], 16;" :: "r"(s), "l"(g));
}
#define CP_COMMIT() asm volatile("cp.async.commit_group;" ::: "memory")
#define CP_WAIT(n)  asm volatile("cp.async.wait_group %0;" :: "n"(n) : "memory")

__device__ __forceinline__ void ldsm4(uint32_t* r, uint32_t addr) {
    asm volatile("ldmatrix.sync.aligned.m8n8.x4.shared.b16 {%0,%1,%2,%3}, [%4];"
                 : "=r"(r[0]), "=r"(r[1]), "=r"(r[2]), "=r"(r[3]) : "r"(addr));
}
__device__ __forceinline__ void mma16(float* c, const uint32_t* a, const uint32_t* b) {
    asm volatile(
        "mma.sync.aligned.m16n8k16.row.col.f32.f16.f16.f32 "
        "{%0,%1,%2,%3}, {%4,%5,%6,%7}, {%8,%9}, {%0,%1,%2,%3};"
        : "+f"(c[0]), "+f"(c[1]), "+f"(c[2]), "+f"(c[3])
        : "r"(a[0]), "r"(a[1]), "r"(a[2]), "r"(a[3]), "r"(b[0]), "r"(b[1]));
}

__device__ __forceinline__ void zero_acc(float (&acc)[2][8][4]) {
#pragma unroll
    for (int mt = 0; mt < 2; ++mt)
#pragma unroll
        for (int nt = 0; nt < 8; ++nt)
#pragma unroll
            for (int q = 0; q < 4; ++q) acc[mt][nt][q] = 0.f;
}

// one k16 step of the 32x64 warptile
__device__ __forceinline__ void k16_step(uint32_t abase, uint32_t bbase,
                                         uint32_t ua_unit, uint32_t ub_unit,
                                         float (&acc)[2][8][4]) {
    uint32_t ua[2][4];
    ldsm4(ua[0], abase + ua_unit);
    ldsm4(ua[1], abase + 16 * 512 + ua_unit);
#pragma unroll
    for (int nt2 = 0; nt2 < 4; ++nt2) {
        uint32_t b[4];
        ldsm4(b, bbase + nt2 * 1024 + ub_unit);
        mma16(acc[0][2 * nt2],     ua[0], b);
        mma16(acc[1][2 * nt2],     ua[1], b);
        mma16(acc[0][2 * nt2 + 1], ua[0], b + 2);
        mma16(acc[1][2 * nt2 + 1], ua[1], b + 2);
    }
}

// rowdot(acc, X_smem swizzled) -> fp16 partials in s_g[wn]
__device__ __forceinline__ void gate_dot(const char* __restrict__ Xs,
                                         const float (&acc)[2][8][4],
                                         int wm, int wn, int lq, int lr,
                                         __half (*s_g)[TM]) {
    float pr[2][2] = {{0.f, 0.f}, {0.f, 0.f}};
#pragma unroll
    for (int mt = 0; mt < 2; ++mt) {
        const int r0 = wm * 32 + mt * 16 + lq;
#pragma unroll
        for (int nt = 0; nt < 8; ++nt) {
            const uint32_t unit = (uint32_t)(((wn * 8 + nt) ^ lq) << 4) + lr * 4;
            float2 v0 = __half22float2(*reinterpret_cast<const __half2*>(Xs + r0 * 512 + unit));
            float2 v1 = __half22float2(*reinterpret_cast<const __half2*>(Xs + (r0 + 8) * 512 + unit));
            pr[mt][0] += acc[mt][nt][0] * v0.x + acc[mt][nt][1] * v0.y;
            pr[mt][1] += acc[mt][nt][2] * v1.x + acc[mt][nt][3] * v1.y;
        }
    }
#pragma unroll
    for (int off = 1; off <= 2; off <<= 1)
#pragma unroll
        for (int mt = 0; mt < 2; ++mt) {
            pr[mt][0] += __shfl_xor_sync(0xFFFFFFFFu, pr[mt][0], off);
            pr[mt][1] += __shfl_xor_sync(0xFFFFFFFFu, pr[mt][1], off);
        }
    if (lr == 0) {
#pragma unroll
        for (int mt = 0; mt < 2; ++mt) {
            s_g[wn][wm * 32 + mt * 16 + lq]     = __float2half_rn(pr[mt][0]);
            s_g[wn][wm * 32 + mt * 16 + lq + 8] = __float2half_rn(pr[mt][1]);
        }
    }
}

__global__ void __launch_bounds__(THREADS, 2)
fused_mma_kernel(const float* __restrict__ i0, const float* __restrict__ i1,
                 float* __restrict__ out) {
    extern __shared__ char dyn[];
    __shared__ __half s_g[4][TM];     // 512 B: gate partials (reused g0 then g1)
    __shared__ __half s_sc[2][TM];    // 256 B: scales s0, s1

    const int tid = threadIdx.x;
    const int l = tid & 31, w = tid >> 5;
    const int wm = w >> 2, wn = w & 3;            // m-split 2, n-split 4
    const int lq = l >> 2, lr = l & 3;
    const size_t rowbase = (size_t)blockIdx.x * TM;
    const uint32_t sb = smem_u32(dyn);

    // ---------- weight staging into 3-buffer ring (swizzled rows) ----------
    auto stage = [&](int j) {
        const int p = j >> 3, c = j & 7;
        const __half* Bs = g_W[p];
        const uint32_t base = sb + WOFF + (uint32_t)(j % 3) * WBUF;
#pragma unroll
        for (int t = 0; t < 4; ++t) {
            const int id = tid + t * THREADS;
            const int n = id >> 2, gk = id & 3;
            cp16(base + (uint32_t)(n * 64) + (uint32_t)((gk ^ ((n >> 1) & 3)) << 4),
                 Bs + n * DIM + c * 32 + gk * 8);
        }
        CP_COMMIT();
    };

    stage(0);                                     // overlap with X prologue
    stage(1);

    // ---------- prologue: LDG fp32 -> cvt -> swizzled STS fp16 ----------
#pragma unroll
    for (int s = 0; s < 2; ++s) {
        const float* src = (s ? i1 : i0) + rowbase * DIM;
        char* dst = dyn + s * XINP;
#pragma unroll
        for (int t = 0; t < 8; ++t) {
            const int id = tid + t * THREADS;
            const int r = id >> 5, cg = id & 31;
            float4 f0 = *reinterpret_cast<const float4*>(src + r * DIM + cg * 8);
            float4 f1 = *reinterpret_cast<const float4*>(src + r * DIM + cg * 8 + 4);
            __half2 h[4];
            h[0] = __floats2half2_rn(f0.x, f0.y);
            h[1] = __floats2half2_rn(f0.z, f0.w);
            h[2] = __floats2half2_rn(f1.x, f1.y);
            h[3] = __floats2half2_rn(f1.z, f1.w);
            *reinterpret_cast<uint4*>(dst + r * 512 + ((cg ^ (r & 7)) << 4)) =
                *reinterpret_cast<const uint4*>(h);
        }
    }
    // (first loop barrier covers X visibility)

    // ---------- per-lane ldsm constants ----------
    const int ae = l & 7;                         // A swizzle key (row&7)
    const uint32_t a_rb = (uint32_t)((wm * 32 + (l & 7) + ((l >> 3) & 1) * 8) * 512);
    const int a_kh = (l >> 4) & 1;                // A k-half unit
    const int b_n = wn * 64 + ((l >> 4) & 1) * 8 + (l & 7);
    const uint32_t b_rb = (uint32_t)(b_n * 64);
    const int sB = (l >> 1) & 3;                  // B swizzle key ((n>>1)&3)
    const uint32_t ub0 = (uint32_t)(((0 + ((l >> 3) & 1)) ^ sB) << 4);   // ks=0
    const uint32_t ub1 = (uint32_t)(((2 + ((l >> 3) & 1)) ^ sB) << 4);   // ks=1

    float acc[2][8][4];
    zero_acc(acc);

    //  p0: A=X1,B=attn1 -> g0 dot X0   p1: A=X0,B=attn2 -> g1 dot X1
    //  p2: A=X0,B=W1 (raw)             p3: A=X1,B=W2 (raw; acc rescaled)
    for (int j = 0; j < NJOBS; ++j) {
        if (j == NJOBS - 1) { CP_WAIT(0); } else { CP_WAIT(1); }
        __syncthreads();                          // single barrier per job

        if (j == 8 || j == 16) {                  // scales from s_g partials
            const int g = (j == 16);
#pragma unroll
            for (int mt = 0; mt < 2; ++mt)
#pragma unroll
                for (int hh = 0; hh < 2; ++hh) {
                    const int r = wm * 32 + mt * 16 + lq + hh * 8;
                    float gg = __half2float(s_g[0][r]) + __half2float(s_g[1][r])
                             + __half2float(s_g[2][r]) + __half2float(s_g[3][r]);
                    s_sc[g][r] = __float2half_rn(1.f + 1.f / (1.f + expf(-gg)));
                }
        }

        if (j + 2 < NJOBS) stage(j + 2);          // overlaps with gemm below

        const int p = j >> 3, c = j & 7;
        const int ainp = (p == 0 || p == 3);
        const uint32_t abase = sb + (uint32_t)ainp * XINP + a_rb;
        const uint32_t bbase = sb + WOFF + (uint32_t)(j % 3) * WBUF + b_rb;
        const int c4 = c * 4;
        const uint32_t ua0 = (uint32_t)(((c4 + 0 + a_kh) ^ ae) << 4);
        const uint32_t ua1 = (uint32_t)(((c4 + 2 + a_kh) ^ ae) << 4);
        k16_step(abase, bbase, ua0, ub0, acc);
        k16_step(abase, bbase, ua1, ub1, acc);

        if (j == 7) {                             // g0 = rowdot(U0, X0)
            gate_dot(dyn, acc, wm, wn, lq, lr, s_g);
            zero_acc(acc);
        }
        if (j == 15) {                            // g1 = rowdot(U1, X1)
            gate_dot(dyn + XINP, acc, wm, wn, lq, lr, s_g);
            zero_acc(acc);
        }
        if (j == 23) {                            // acc = P0 -> scale by s0/s1
#pragma unroll
            for (int mt = 0; mt < 2; ++mt) {
                const int r0 = wm * 32 + mt * 16 + lq;
                const float rt0 = __half2float(s_sc[0][r0]) / __half2float(s_sc[1][r0]);
                const float rt1 = __half2float(s_sc[0][r0 + 8]) / __half2float(s_sc[1][r0 + 8]);
#pragma unroll
                for (int nt = 0; nt < 8; ++nt) {
                    acc[mt][nt][0] *= rt0; acc[mt][nt][1] *= rt0;
                    acc[mt][nt][2] *= rt1; acc[mt][nt][3] *= rt1;
                }
            }
        }
    }

    // epilogue: out = s1 * acc = s0*P0 + s1*P1
#pragma unroll
    for (int mt = 0; mt < 2; ++mt) {
        const int r0 = wm * 32 + mt * 16 + lq;
        const float f0 = __half2float(s_sc[1][r0]);
        const float f1 = __half2float(s_sc[1][r0 + 8]);
#pragma unroll
        for (int nt = 0; nt < 8; ++nt) {
            const int cb = wn * 64 + nt * 8 + lr * 2;
            float2 v0 = make_float2(acc[mt][nt][0] * f0, acc[mt][nt][1] * f0);
            float2 v1 = make_float2(acc[mt][nt][2] * f1, acc[mt][nt][3] * f1);
            *reinterpret_cast<float2*>(out + (rowbase + r0) * DIM + cb) = v0;
            *reinterpret_cast<float2*>(out + (rowbase + r0 + 8) * DIM + cb) = v1;
        }
    }
}

// ---- prep: weights transposed to [n][k] fp16 ----
__global__ void wprep_kernel(const float* __restrict__ w1, const float* __restrict__ w2,
                             const float* __restrict__ a1, const float* __restrict__ a2) {
    const int z = blockIdx.x;
    const float* src = (z == 0) ? a1 : (z == 1) ? a2 : (z == 2) ? w1 : w2;
    const int n = threadIdx.x;
    const int k0 = blockIdx.y * 32;
    for (int k = k0; k < k0 + 32; ++k)
        g_W[z][n * DIM + k] = __float2half_rn(src[k * DIM + n]);
}

extern "C" void kernel_launch(void* const* d_in, const int* in_sizes, int n_in,
                              void* d_out, int out_size) {
    const float* i0 = (const float*)d_in[0];
    const float* i1 = (const float*)d_in[1];
    const float* W1 = (const float*)d_in[2];
    const float* W2 = (const float*)d_in[3];
    const float* A1 = (const float*)d_in[4];
    const float* A2 = (const float*)d_in[5];
    float* out = (float*)d_out;

    wprep_kernel<<<dim3(4, 8), 256>>>(W1, W2, A1, A2);

    cudaFuncSetAttribute(fused_mma_kernel,
                         cudaFuncAttributeMaxDynamicSharedMemorySize, SMEM_BYTES);
    const int rows = in_sizes[0] / DIM;           // 65536
    fused_mma_kernel<<<rows / TM, THREADS, SMEM_BYTES>>>(i0, i1, out);
    (void)n_in; (void)out_size;
}